// round 2
// baseline (speedup 1.0000x reference)
#include <cuda_runtime.h>
#include <cuda_bf16.h>
#include <math_constants.h>

// Problem constants (fixed shapes per metadata)
#define NA   4096      // batch rows used (16384 / 4)
#define NB   4096      // output rows
#define DIMK 128       // feature dim

// ---------------- scratch (no allocations allowed) ----------------
__device__ __align__(16) float g_sqA[NA];
__device__ __align__(16) float g_sqB[NB];
__device__ __align__(16) float g_keyB[NB];
__device__ __align__(16) float g_DBB[(size_t)NB * NB];   // 64 MB, fits L2

// ---------------- K1: squared norms ----------------
__global__ __launch_bounds__(256) void sqnorm_kernel(const float* __restrict__ batch,
                                                     const float* __restrict__ output) {
    int row  = blockIdx.x * 8 + (threadIdx.x >> 5);   // 8 warps/block, 1024 blocks -> 8192 rows
    int lane = threadIdx.x & 31;
    const float* src = (row < NA) ? (batch + (size_t)row * DIMK)
                                  : (output + (size_t)(row - NA) * DIMK);
    float s = 0.f;
    #pragma unroll
    for (int k = lane; k < DIMK; k += 32) { float v = src[k]; s += v * v; }
    #pragma unroll
    for (int o = 16; o; o >>= 1) s += __shfl_down_sync(0xffffffffu, s, o);
    if (lane == 0) {
        if (row < NA) g_sqA[row] = s;
        else          g_sqB[row - NA] = s;
    }
}

// ---------------- K2: keyB[b] = min over A of dist(b,a) ----------------
__global__ __launch_bounds__(256) void key_init_kernel(const float* __restrict__ P,  // B points [NB][128]
                                                       const float* __restrict__ Q)  // A points [NA][128]
{
    __shared__ float sP[64][17];
    __shared__ float sQ[64][17];
    __shared__ float red[64][17];

    const int tid = threadIdx.x;
    const int tx  = tid & 15;        // column group
    const int ty  = tid >> 4;        // row group
    const int m0  = blockIdx.x * 64; // B rows

    const int lr  = tid >> 2;        // 0..63  load row
    const int lc4 = (tid & 3) * 4;   // 0,4,8,12 load col (float4)

    float minv[4] = {CUDART_INF_F, CUDART_INF_F, CUDART_INF_F, CUDART_INF_F};

    for (int n0 = 0; n0 < NA; n0 += 64) {
        float acc[4][4];
        #pragma unroll
        for (int i = 0; i < 4; i++)
            #pragma unroll
            for (int j = 0; j < 4; j++) acc[i][j] = 0.f;

        for (int kk = 0; kk < DIMK; kk += 16) {
            float4 vp = *(const float4*)&P[(size_t)(m0 + lr) * DIMK + kk + lc4];
            float4 vq = *(const float4*)&Q[(size_t)(n0 + lr) * DIMK + kk + lc4];
            __syncthreads();
            sP[lr][lc4+0] = vp.x; sP[lr][lc4+1] = vp.y; sP[lr][lc4+2] = vp.z; sP[lr][lc4+3] = vp.w;
            sQ[lr][lc4+0] = vq.x; sQ[lr][lc4+1] = vq.y; sQ[lr][lc4+2] = vq.z; sQ[lr][lc4+3] = vq.w;
            __syncthreads();
            #pragma unroll
            for (int k = 0; k < 16; k++) {
                float pa[4], qa[4];
                #pragma unroll
                for (int i = 0; i < 4; i++) pa[i] = sP[ty*4+i][k];
                #pragma unroll
                for (int j = 0; j < 4; j++) qa[j] = sQ[tx*4+j][k];
                #pragma unroll
                for (int i = 0; i < 4; i++)
                    #pragma unroll
                    for (int j = 0; j < 4; j++) acc[i][j] += pa[i] * qa[j];
            }
        }
        // fold min over this A tile: track (|a|^2 - 2 dot); |b|^2 added later
        #pragma unroll
        for (int j = 0; j < 4; j++) {
            float sq = g_sqA[n0 + tx*4 + j];
            #pragma unroll
            for (int i = 0; i < 4; i++) {
                float v = sq - 2.f * acc[i][j];
                minv[i] = fminf(minv[i], v);
            }
        }
    }
    // reduce across tx (16 threads per row)
    __syncthreads();
    #pragma unroll
    for (int i = 0; i < 4; i++) red[ty*4+i][tx] = minv[i];
    __syncthreads();
    if (tid < 64) {
        float m = CUDART_INF_F;
        #pragma unroll
        for (int t = 0; t < 16; t++) m = fminf(m, red[tid][t]);
        float d2 = g_sqB[m0 + tid] + m;
        g_keyB[m0 + tid] = sqrtf(fmaxf(d2, 0.f));
    }
}

// ---------------- K3: full B-B distance matrix ----------------
__global__ __launch_bounds__(256) void dbb_kernel(const float* __restrict__ P)  // B points
{
    __shared__ float sP[64][17];
    __shared__ float sQ[64][17];

    const int tid = threadIdx.x;
    const int tx  = tid & 15;
    const int ty  = tid >> 4;
    const int m0  = blockIdx.y * 64;
    const int n0  = blockIdx.x * 64;

    const int lr  = tid >> 2;
    const int lc4 = (tid & 3) * 4;

    float acc[4][4];
    #pragma unroll
    for (int i = 0; i < 4; i++)
        #pragma unroll
        for (int j = 0; j < 4; j++) acc[i][j] = 0.f;

    for (int kk = 0; kk < DIMK; kk += 16) {
        float4 vp = *(const float4*)&P[(size_t)(m0 + lr) * DIMK + kk + lc4];
        float4 vq = *(const float4*)&P[(size_t)(n0 + lr) * DIMK + kk + lc4];
        __syncthreads();
        sP[lr][lc4+0] = vp.x; sP[lr][lc4+1] = vp.y; sP[lr][lc4+2] = vp.z; sP[lr][lc4+3] = vp.w;
        sQ[lr][lc4+0] = vq.x; sQ[lr][lc4+1] = vq.y; sQ[lr][lc4+2] = vq.z; sQ[lr][lc4+3] = vq.w;
        __syncthreads();
        #pragma unroll
        for (int k = 0; k < 16; k++) {
            float pa[4], qa[4];
            #pragma unroll
            for (int i = 0; i < 4; i++) pa[i] = sP[ty*4+i][k];
            #pragma unroll
            for (int j = 0; j < 4; j++) qa[j] = sQ[tx*4+j][k];
            #pragma unroll
            for (int i = 0; i < 4; i++)
                #pragma unroll
                for (int j = 0; j < 4; j++) acc[i][j] += pa[i] * qa[j];
        }
    }
    #pragma unroll
    for (int i = 0; i < 4; i++) {
        int bi = m0 + ty*4 + i;
        float sqi = g_sqB[bi];
        #pragma unroll
        for (int j = 0; j < 4; j++) {
            int bj = n0 + tx*4 + j;
            float d2 = sqi + g_sqB[bj] - 2.f * acc[i][j];
            g_DBB[(size_t)bi * NB + bj] = sqrtf(fmaxf(d2, 0.f));
        }
    }
}

// ---------------- K4: single-block Prim over supernode + 4096 B points ----------------
// Keys live in registers (16 per thread). Explicit visited mask per thread:
// a visited element's key is forced to +INF after every relaxation, so it can
// never be re-extracted (the relaxation min would otherwise resurrect it).
__device__ __forceinline__ void block_argmin(float lv, unsigned li, int t,
                                             float* s_val, unsigned* s_idx,
                                             float* s_resv, unsigned* s_resi,
                                             float& rv, unsigned& ri)
{
    unsigned vb   = __float_as_uint(lv);                 // keys >= 0 or +INF -> bit order = fp order
    unsigned wmin = __reduce_min_sync(0xffffffffu, vb);
    unsigned cand = (vb == wmin) ? li : 0xffffffffu;
    unsigned widx = __reduce_min_sync(0xffffffffu, cand);
    int warp = t >> 5, lane = t & 31;
    if (lane == 0) { s_val[warp] = __uint_as_float(wmin); s_idx[warp] = widx; }
    __syncthreads();
    if (t < 32) {
        unsigned vb2 = (lane < 8) ? __float_as_uint(s_val[lane]) : 0x7f800000u;
        unsigned li2 = (lane < 8) ? s_idx[lane] : 0xffffffffu;
        unsigned m2  = __reduce_min_sync(0xffffffffu, vb2);
        unsigned c2  = (vb2 == m2) ? li2 : 0xffffffffu;
        unsigned i2  = __reduce_min_sync(0xffffffffu, c2);
        if (lane == 0) { *s_resv = __uint_as_float(m2); *s_resi = i2; }
    }
    __syncthreads();
    rv = *s_resv; ri = *s_resi;
}

__global__ __launch_bounds__(256) void prim_kernel(float* __restrict__ out)
{
    const int t = threadIdx.x;
    __shared__ float    s_val[8];
    __shared__ unsigned s_idx[8];
    __shared__ float    s_resv;
    __shared__ unsigned s_resi;

    float4 key[4];
    #pragma unroll
    for (int c = 0; c < 4; c++)
        key[c] = *(const float4*)&g_keyB[c * 1024 + t * 4];

    unsigned vis = 0u;   // bit (c*4+e) = element e of chunk c is in the tree

    // initial local argmin (nothing visited yet)
    float lv = CUDART_INF_F; unsigned li = 0;
    #pragma unroll
    for (int c = 0; c < 4; c++) {
        unsigned base = c * 1024 + t * 4;
        float4 k = key[c];
        if (k.x < lv) { lv = k.x; li = base + 0; }
        if (k.y < lv) { lv = k.y; li = base + 1; }
        if (k.z < lv) { lv = k.z; li = base + 2; }
        if (k.w < lv) { lv = k.w; li = base + 3; }
    }
    float rv; unsigned ri;
    block_argmin(lv, li, t, s_val, s_idx, &s_resv, &s_resi, rv, ri);

    float total = 0.f;
    for (int step = 0; step < NB; step++) {
        total += rv;
        if (step == NB - 1) break;
        const float4* row = (const float4*)(g_DBB + (size_t)ri * NB);
        lv = CUDART_INF_F; li = 0;
        #pragma unroll
        for (int c = 0; c < 4; c++) {
            float4 d = row[c * 256 + t];
            float4 k = key[c];
            unsigned base = c * 1024 + t * 4;
            if (ri - base < 4u)                 // this thread owns the extracted node
                vis |= 1u << (c * 4 + (ri - base));
            unsigned mb = vis >> (c * 4);
            k.x = (mb & 1u) ? CUDART_INF_F : fminf(k.x, d.x);
            k.y = (mb & 2u) ? CUDART_INF_F : fminf(k.y, d.y);
            k.z = (mb & 4u) ? CUDART_INF_F : fminf(k.z, d.z);
            k.w = (mb & 8u) ? CUDART_INF_F : fminf(k.w, d.w);
            key[c] = k;
            if (k.x < lv) { lv = k.x; li = base + 0; }
            if (k.y < lv) { lv = k.y; li = base + 1; }
            if (k.z < lv) { lv = k.z; li = base + 2; }
            if (k.w < lv) { lv = k.w; li = base + 3; }
        }
        block_argmin(lv, li, t, s_val, s_idx, &s_resv, &s_resi, rv, ri);
    }
    if (t == 0) out[0] = total;
}

// ---------------- launch ----------------
extern "C" void kernel_launch(void* const* d_in, const int* in_sizes, int n_in,
                              void* d_out, int out_size)
{
    const float* batch  = (const float*)d_in[0];   // [16384,128]
    const float* output = (const float*)d_in[1];   // [4096,128]
    float* out = (float*)d_out;

    // K1: squared norms of 8192 points (A = batch[:4096], B = output)
    sqnorm_kernel<<<(NA + NB) / 8, 256>>>(batch, output);

    // K2: keyB = distance from each B point to nearest A point
    key_init_kernel<<<NB / 64, 256>>>(output, batch);

    // K3: full B-B distance matrix
    dim3 g3(NA / 64, NB / 64);
    dbb_kernel<<<g3, 256>>>(output);

    // K4: sequential Prim (supernode + 4096 B nodes), single block
    prim_kernel<<<1, 256>>>(out);
}

// round 3
// speedup vs baseline: 4.5224x; 4.5224x over previous
#include <cuda_runtime.h>
#include <cuda_bf16.h>
#include <math_constants.h>

// Problem constants (fixed shapes per metadata)
#define NA    4096     // batch rows used (16384 / 4)
#define NB    4096     // output rows
#define DIMK  128      // feature dim
#define NN    4097     // NB B-nodes + 1 supernode (all of A, internally weight-0)
#define SUPER 4096
#define ROUNDS 13
#define ULLMAX 0xFFFFFFFFFFFFFFFFULL

// ---------------- scratch (no allocations allowed) ----------------
__device__ __align__(16) float    g_sqA[NA];
__device__ __align__(16) float    g_sqB[NB];
__device__ __align__(16) float    g_keyB[NB];
__device__ __align__(16) unsigned g_KEY[(size_t)NB * NB];  // 64 MB: (trunc20 dist | col12)
__device__ int                g_comp[NN];
__device__ unsigned long long g_best[NN];
__device__ float              g_total;
__device__ int                g_done;

// ---------------- K1: squared norms ----------------
__global__ __launch_bounds__(256) void sqnorm_kernel(const float* __restrict__ batch,
                                                     const float* __restrict__ output) {
    int row  = blockIdx.x * 8 + (threadIdx.x >> 5);
    int lane = threadIdx.x & 31;
    const float* src = (row < NA) ? (batch + (size_t)row * DIMK)
                                  : (output + (size_t)(row - NA) * DIMK);
    float s = 0.f;
    #pragma unroll
    for (int k = lane; k < DIMK; k += 32) { float v = src[k]; s += v * v; }
    #pragma unroll
    for (int o = 16; o; o >>= 1) s += __shfl_down_sync(0xffffffffu, s, o);
    if (lane == 0) {
        if (row < NA) g_sqA[row] = s;
        else          g_sqB[row - NA] = s;
    }
}

// ---------------- K2: keyB[b] = min over A of dist(b,a) (exact fp32) ----------------
__global__ __launch_bounds__(256) void key_init_kernel(const float* __restrict__ P,  // B [NB][128]
                                                       const float* __restrict__ Q)  // A [NA][128]
{
    __shared__ float sP[64][17];
    __shared__ float sQ[64][17];
    __shared__ float red[64][17];

    const int tid = threadIdx.x;
    const int tx  = tid & 15;
    const int ty  = tid >> 4;
    const int m0  = blockIdx.x * 64;
    const int lr  = tid >> 2;
    const int lc4 = (tid & 3) * 4;

    float minv[4] = {CUDART_INF_F, CUDART_INF_F, CUDART_INF_F, CUDART_INF_F};

    for (int n0 = 0; n0 < NA; n0 += 64) {
        float acc[4][4];
        #pragma unroll
        for (int i = 0; i < 4; i++)
            #pragma unroll
            for (int j = 0; j < 4; j++) acc[i][j] = 0.f;

        for (int kk = 0; kk < DIMK; kk += 16) {
            float4 vp = *(const float4*)&P[(size_t)(m0 + lr) * DIMK + kk + lc4];
            float4 vq = *(const float4*)&Q[(size_t)(n0 + lr) * DIMK + kk + lc4];
            __syncthreads();
            sP[lr][lc4+0] = vp.x; sP[lr][lc4+1] = vp.y; sP[lr][lc4+2] = vp.z; sP[lr][lc4+3] = vp.w;
            sQ[lr][lc4+0] = vq.x; sQ[lr][lc4+1] = vq.y; sQ[lr][lc4+2] = vq.z; sQ[lr][lc4+3] = vq.w;
            __syncthreads();
            #pragma unroll
            for (int k = 0; k < 16; k++) {
                float pa[4], qa[4];
                #pragma unroll
                for (int i = 0; i < 4; i++) pa[i] = sP[ty*4+i][k];
                #pragma unroll
                for (int j = 0; j < 4; j++) qa[j] = sQ[tx*4+j][k];
                #pragma unroll
                for (int i = 0; i < 4; i++)
                    #pragma unroll
                    for (int j = 0; j < 4; j++) acc[i][j] += pa[i] * qa[j];
            }
        }
        #pragma unroll
        for (int j = 0; j < 4; j++) {
            float sq = g_sqA[n0 + tx*4 + j];
            #pragma unroll
            for (int i = 0; i < 4; i++) {
                float v = sq - 2.f * acc[i][j];
                minv[i] = fminf(minv[i], v);
            }
        }
    }
    __syncthreads();
    #pragma unroll
    for (int i = 0; i < 4; i++) red[ty*4+i][tx] = minv[i];
    __syncthreads();
    if (tid < 64) {
        float m = CUDART_INF_F;
        #pragma unroll
        for (int t = 0; t < 16; t++) m = fminf(m, red[tid][t]);
        float d2 = g_sqB[m0 + tid] + m;
        g_keyB[m0 + tid] = sqrtf(fmaxf(d2, 0.f));
    }
}

// ---------------- K3: B-B packed key matrix: (fp32bits(d) & ~0xFFF) | col ----------------
__global__ __launch_bounds__(256) void dbb_kernel(const float* __restrict__ P)
{
    __shared__ float sP[64][17];
    __shared__ float sQ[64][17];

    const int tid = threadIdx.x;
    const int tx  = tid & 15;
    const int ty  = tid >> 4;
    const int m0  = blockIdx.y * 64;
    const int n0  = blockIdx.x * 64;
    const int lr  = tid >> 2;
    const int lc4 = (tid & 3) * 4;

    float acc[4][4];
    #pragma unroll
    for (int i = 0; i < 4; i++)
        #pragma unroll
        for (int j = 0; j < 4; j++) acc[i][j] = 0.f;

    for (int kk = 0; kk < DIMK; kk += 16) {
        float4 vp = *(const float4*)&P[(size_t)(m0 + lr) * DIMK + kk + lc4];
        float4 vq = *(const float4*)&P[(size_t)(n0 + lr) * DIMK + kk + lc4];
        __syncthreads();
        sP[lr][lc4+0] = vp.x; sP[lr][lc4+1] = vp.y; sP[lr][lc4+2] = vp.z; sP[lr][lc4+3] = vp.w;
        sQ[lr][lc4+0] = vq.x; sQ[lr][lc4+1] = vq.y; sQ[lr][lc4+2] = vq.z; sQ[lr][lc4+3] = vq.w;
        __syncthreads();
        #pragma unroll
        for (int k = 0; k < 16; k++) {
            float pa[4], qa[4];
            #pragma unroll
            for (int i = 0; i < 4; i++) pa[i] = sP[ty*4+i][k];
            #pragma unroll
            for (int j = 0; j < 4; j++) qa[j] = sQ[tx*4+j][k];
            #pragma unroll
            for (int i = 0; i < 4; i++)
                #pragma unroll
                for (int j = 0; j < 4; j++) acc[i][j] += pa[i] * qa[j];
        }
    }
    #pragma unroll
    for (int i = 0; i < 4; i++) {
        int bi = m0 + ty*4 + i;
        float sqi = g_sqB[bi];
        #pragma unroll
        for (int j = 0; j < 4; j++) {
            int bj = n0 + tx*4 + j;
            float d2 = sqi + g_sqB[bj] - 2.f * acc[i][j];
            float d  = sqrtf(fmaxf(d2, 0.f));
            g_KEY[(size_t)bi * NB + bj] = (__float_as_uint(d) & 0xFFFFF000u) | (unsigned)bj;
        }
    }
}

// ---------------- init ----------------
__global__ __launch_bounds__(1024) void init_kernel() {
    int t = threadIdx.x;
    for (int x = t; x < NN; x += 1024) {
        g_comp[x] = x;
        g_best[x] = ULLMAX;
    }
    if (t == 0) { g_total = 0.f; g_done = 0; }
}

// ---------------- Boruvka scan: per-component min outgoing edge ----------------
// 512 blocks x 256 threads; each warp owns one matrix row (one B node).
__global__ __launch_bounds__(256) void scan_kernel() {
    if (g_done) return;
    __shared__ __align__(16) int sComp[NN + 3];
    const int tid = threadIdx.x;
    for (int x = tid; x < NN; x += 256) sComp[x] = g_comp[x];
    __syncthreads();

    const int warp = tid >> 5, lane = tid & 31;
    const int i    = blockIdx.x * 8 + warp;
    const int cu   = sComp[i];
    const int csup = sComp[SUPER];

    const uint4* row  = (const uint4*)(g_KEY + (size_t)i * NB);
    const int4*  cmp4 = (const int4*)sComp;

    unsigned best32 = 0xFFFFFFFFu;
    #pragma unroll 8
    for (int c = 0; c < 32; c++) {
        uint4 k  = row[c * 32 + lane];
        int4  cc = cmp4[c * 32 + lane];
        best32 = min(best32, (cc.x == cu) ? 0xFFFFFFFFu : k.x);
        best32 = min(best32, (cc.y == cu) ? 0xFFFFFFFFu : k.y);
        best32 = min(best32, (cc.z == cu) ? 0xFFFFFFFFu : k.z);
        best32 = min(best32, (cc.w == cu) ? 0xFFFFFFFFu : k.w);
    }
    #pragma unroll
    for (int o = 16; o; o >>= 1) best32 = min(best32, __shfl_xor_sync(0xffffffffu, best32, o));

    if (lane == 0) {
        unsigned long long kb = ULLMAX;
        if (best32 != 0xFFFFFFFFu) {
            unsigned j  = best32 & 0xFFFu;
            unsigned tw = best32 >> 12;
            unsigned lo = min((unsigned)i, j), hi = max((unsigned)i, j);
            kb = ((unsigned long long)tw << 26) | ((unsigned long long)lo << 13) | hi;
        }
        if (cu != csup) {
            unsigned tws = __float_as_uint(g_keyB[i]) >> 12;
            unsigned long long ks = ((unsigned long long)tws << 26) |
                                    ((unsigned long long)(unsigned)i << 13) | SUPER;
            kb = min(kb, ks);
            atomicMin(&g_best[csup], ks);        // feed supernode's component too
        }
        if (kb != ULLMAX) atomicMin(&g_best[cu], kb);
    }
}

// ---------------- Boruvka merge: select edges, hook, compress, accumulate ----------------
__global__ __launch_bounds__(1024) void merge_kernel(const float* __restrict__ P,
                                                     float* __restrict__ out) {
    const int tid = threadIdx.x;
    __shared__ int   sT[NN];
    __shared__ float sRed[32];
    __shared__ int   sCnt[32];

    if (g_done) { if (tid == 0) out[0] = g_total; return; }

    // A1: snapshot target roots (reads comp, no writes)
    for (int x = tid; x < NN; x += 1024) {
        int t = -1;
        if (g_comp[x] == x) {
            unsigned long long k = g_best[x];
            if (k != ULLMAX) {
                int u  = (int)((k >> 13) & 0x1FFFu);
                int v  = (int)(k & 0x1FFFu);
                int c1 = g_comp[u], c2 = g_comp[v];
                t = (c1 == x) ? c2 : c1;
            }
        }
        sT[x] = t;
    }
    __syncthreads();

    // A2: count each selected edge once (mutual pair -> smaller root), hook roots
    float lsum = 0.f;
    for (int x = tid; x < NN; x += 1024) {
        int t = sT[x];
        if (t >= 0) {
            unsigned long long k = g_best[x];
            bool mutual = (g_best[t] == k);
            if (!mutual || x < t) {
                int u = (int)((k >> 13) & 0x1FFFu);
                int v = (int)(k & 0x1FFFu);
                float w;
                if (v == SUPER) {
                    w = g_keyB[u];
                } else {
                    const float* pu = P + (size_t)u * DIMK;
                    const float* pv = P + (size_t)v * DIMK;
                    float s = 0.f;
                    #pragma unroll
                    for (int d = 0; d < DIMK; d++) { float df = pu[d] - pv[d]; s += df * df; }
                    w = sqrtf(s);
                }
                lsum += w;
            }
            if (!(mutual && x < t)) g_comp[x] = t;   // mutual smaller root stays
        }
    }
    #pragma unroll
    for (int o = 16; o; o >>= 1) lsum += __shfl_xor_sync(0xffffffffu, lsum, o);
    if ((tid & 31) == 0) sRed[tid >> 5] = lsum;
    __syncthreads();

    // B: pointer jumping to full compression (depth <= NN -> 13 halvings)
    for (int it = 0; it < 13; it++) {
        for (int x = tid; x < NN; x += 1024) {
            int c = g_comp[x];
            g_comp[x] = g_comp[c];
        }
        __syncthreads();
    }

    // C: count components, reset bests, accumulate total
    int lcnt = 0;
    for (int x = tid; x < NN; x += 1024) {
        lcnt += (g_comp[x] == x);
        g_best[x] = ULLMAX;
    }
    #pragma unroll
    for (int o = 16; o; o >>= 1) lcnt += __shfl_xor_sync(0xffffffffu, lcnt, o);
    if ((tid & 31) == 0) sCnt[tid >> 5] = lcnt;
    __syncthreads();

    if (tid == 0) {
        float rs = 0.f; int cnt = 0;
        #pragma unroll
        for (int w = 0; w < 32; w++) { rs += sRed[w]; cnt += sCnt[w]; }
        g_total += rs;
        if (cnt <= 1) g_done = 1;
        out[0] = g_total;
    }
}

// ---------------- launch ----------------
extern "C" void kernel_launch(void* const* d_in, const int* in_sizes, int n_in,
                              void* d_out, int out_size)
{
    const float* batch  = (const float*)d_in[0];   // [16384,128]
    const float* output = (const float*)d_in[1];   // [4096,128]
    float* out = (float*)d_out;

    sqnorm_kernel<<<(NA + NB) / 8, 256>>>(batch, output);
    key_init_kernel<<<NB / 64, 256>>>(output, batch);
    dim3 g3(NB / 64, NB / 64);
    dbb_kernel<<<g3, 256>>>(output);
    init_kernel<<<1, 1024>>>();

    for (int r = 0; r < ROUNDS; r++) {
        scan_kernel<<<NB / 8, 256>>>();
        merge_kernel<<<1, 1024>>>(output, out);
    }
}

// round 4
// speedup vs baseline: 6.4447x; 1.4251x over previous
#include <cuda_runtime.h>
#include <cuda_bf16.h>
#include <math_constants.h>

#define NA    4096
#define NB    4096
#define DIMK  128
#define NN    4097
#define SUPER 4096
#define ULLMAX 0xFFFFFFFFFFFFFFFFULL

typedef unsigned long long ull;

// ---------------- scratch ----------------
__device__ __align__(16) float    g_sqA[NA];
__device__ __align__(16) float    g_sqB[NB];
__device__ __align__(16) float    g_keyB[NB];
__device__ __align__(16) unsigned g_key2min[NB];   // fp32 bits of min clamped d^2 (B->A)
__device__ __align__(16) unsigned g_row1[NB];      // round-1 per-row min packed key
__device__ __align__(16) unsigned g_KEY[(size_t)NB * NB];  // 64MB packed (w20|col12)
__device__ int  g_comp[NN];
__device__ ull  g_best[NN];
__device__ float g_total;
__device__ int   g_done;

__device__ __forceinline__ int swc(int k, int c) { return c ^ (((k >> 2) & 15) << 2); }

// ---------------- K1: squared norms ----------------
__global__ __launch_bounds__(256) void sqnorm_kernel(const float* __restrict__ batch,
                                                     const float* __restrict__ output) {
    int row  = blockIdx.x * 8 + (threadIdx.x >> 5);
    int lane = threadIdx.x & 31;
    const float* src = (row < NA) ? (batch + (size_t)row * DIMK)
                                  : (output + (size_t)(row - NA) * DIMK);
    float s = 0.f;
    #pragma unroll
    for (int k = lane; k < DIMK; k += 32) { float v = src[k]; s += v * v; }
    #pragma unroll
    for (int o = 16; o; o >>= 1) s += __shfl_down_sync(0xffffffffu, s, o);
    if (lane == 0) {
        if (row < NA) g_sqA[row] = s;
        else          g_sqB[row - NA] = s;
    }
}

// ---------------- init ----------------
__global__ __launch_bounds__(1024) void init_kernel() {
    int i = blockIdx.x * blockDim.x + threadIdx.x;
    int stride = gridDim.x * blockDim.x;
    for (int x = i; x < NN; x += stride) { g_comp[x] = x; g_best[x] = ULLMAX; }
    for (int x = i; x < NB; x += stride) { g_row1[x] = 0xFFFFFFFFu; g_key2min[x] = 0x7F800000u; }
    if (i == 0) { g_total = 0.f; g_done = 0; }
}

// ---------------- shared-tile loaders (transposed [k][row], XOR swizzle) ----------------
__device__ __forceinline__ void load_tileT(float* st, const float* __restrict__ g) {
    int tid = threadIdx.x;
    #pragma unroll
    for (int it = 0; it < 8; it++) {
        int f  = tid + it * 256;
        int r  = f >> 5;              // 32 float4 per 128-float row
        int kq = (f & 31) << 2;
        float4 v = *(const float4*)(g + (size_t)r * DIMK + kq);
        int c = swc(kq, r);
        st[(kq + 0) * 64 + c] = v.x;
        st[(kq + 1) * 64 + c] = v.y;
        st[(kq + 2) * 64 + c] = v.z;
        st[(kq + 3) * 64 + c] = v.w;
    }
}

__device__ __forceinline__ void load_chunkT(float* st, const float* __restrict__ g, int kc) {
    int tid = threadIdx.x;
    #pragma unroll
    for (int it = 0; it < 2; it++) {
        int f  = tid + it * 256;
        int r  = f >> 3;              // 8 float4 per 32-float chunk row
        int kq = (f & 7) << 2;        // local k within chunk
        float4 v = *(const float4*)(g + (size_t)r * DIMK + kc * 32 + kq);
        int c = swc(kq, r);
        st[(kq + 0) * 64 + c] = v.x;
        st[(kq + 1) * 64 + c] = v.y;
        st[(kq + 2) * 64 + c] = v.z;
        st[(kq + 3) * 64 + c] = v.w;
    }
}

__device__ __forceinline__ void gemm_chunk(const float* sPt, const float* sQt,
                                           int tx, int ty, float acc[4][4], int kc) {
    #pragma unroll 8
    for (int kl = 0; kl < 32; kl++) {
        int kg = kc * 32 + kl;
        float4 pa = *(const float4*)&sPt[kg * 64 + swc(kg, ty * 4)];
        float4 qa = *(const float4*)&sQt[kl * 64 + swc(kl, tx * 4)];
        float p[4] = {pa.x, pa.y, pa.z, pa.w};
        float q[4] = {qa.x, qa.y, qa.z, qa.w};
        #pragma unroll
        for (int i = 0; i < 4; i++)
            #pragma unroll
            for (int j = 0; j < 4; j++) acc[i][j] += p[i] * q[j];
    }
}

// ---------------- K2: min_a dist^2(b,a), atomicMin over column groups ----------------
__global__ __launch_bounds__(256) void key_init_kernel(const float* __restrict__ P,  // B
                                                       const float* __restrict__ Q)  // A
{
    __shared__ __align__(16) float sPt[DIMK * 64];
    __shared__ __align__(16) float sQt[32 * 64];
    const int tid = threadIdx.x, tx = tid & 15, ty = tid >> 4;
    const int m0 = blockIdx.x * 64;
    const int a0 = blockIdx.y * 512;

    load_tileT(sPt, P + (size_t)m0 * DIMK);

    float minv[4] = {CUDART_INF_F, CUDART_INF_F, CUDART_INF_F, CUDART_INF_F};

    for (int n0 = a0; n0 < a0 + 512; n0 += 64) {
        float acc[4][4] = {};
        for (int kc = 0; kc < 4; kc++) {
            __syncthreads();
            load_chunkT(sQt, Q + (size_t)n0 * DIMK, kc);
            __syncthreads();
            gemm_chunk(sPt, sQt, tx, ty, acc, kc);
        }
        #pragma unroll
        for (int j = 0; j < 4; j++) {
            float sq = g_sqA[n0 + tx * 4 + j];
            #pragma unroll
            for (int i = 0; i < 4; i++)
                minv[i] = fminf(minv[i], sq - 2.f * acc[i][j]);
        }
    }
    #pragma unroll
    for (int i = 0; i < 4; i++) {
        float m = minv[i];
        #pragma unroll
        for (int o = 8; o; o >>= 1) m = fminf(m, __shfl_xor_sync(0xffffffffu, m, o));
        if (tx == 0) {
            int row = m0 + ty * 4 + i;
            float v = fmaxf(g_sqB[row] + m, 0.f);
            atomicMin(&g_key2min[row], __float_as_uint(v));
        }
    }
}

// ---------------- K3: packed B-B key matrix + fused round-1 row min ----------------
__global__ __launch_bounds__(256) void dbb_kernel(const float* __restrict__ P)
{
    __shared__ __align__(16) float sPt[DIMK * 64];
    __shared__ __align__(16) float sQt[32 * 64];
    const int tid = threadIdx.x, tx = tid & 15, ty = tid >> 4;
    const int m0 = blockIdx.y * 64;
    const int n0 = blockIdx.x * 64;

    load_tileT(sPt, P + (size_t)m0 * DIMK);

    float acc[4][4] = {};
    for (int kc = 0; kc < 4; kc++) {
        __syncthreads();
        load_chunkT(sQt, P + (size_t)n0 * DIMK, kc);
        __syncthreads();
        gemm_chunk(sPt, sQt, tx, ty, acc, kc);
    }

    unsigned rmin[4] = {0xFFFFFFFFu, 0xFFFFFFFFu, 0xFFFFFFFFu, 0xFFFFFFFFu};
    #pragma unroll
    for (int i = 0; i < 4; i++) {
        int bi = m0 + ty * 4 + i;
        float sqi = g_sqB[bi];
        unsigned pk[4];
        #pragma unroll
        for (int j = 0; j < 4; j++) {
            int bj = n0 + tx * 4 + j;
            float d2 = sqi + g_sqB[bj] - 2.f * acc[i][j];
            float d  = sqrtf(fmaxf(d2, 0.f));
            pk[j] = (__float_as_uint(d) & 0xFFFFF000u) | (unsigned)bj;
            if (bj != bi) rmin[i] = min(rmin[i], pk[j]);
        }
        *(uint4*)&g_KEY[(size_t)bi * NB + n0 + tx * 4] = make_uint4(pk[0], pk[1], pk[2], pk[3]);
    }
    #pragma unroll
    for (int i = 0; i < 4; i++) {
        unsigned m = rmin[i];
        #pragma unroll
        for (int o = 8; o; o >>= 1) m = min(m, __shfl_xor_sync(0xffffffffu, m, o));
        if (tx == 0) atomicMin(&g_row1[m0 + ty * 4 + i], m);
    }
}

// ---------------- round-1 best assembly (replaces first scan) ----------------
__global__ __launch_bounds__(1024) void round1_kernel() {
    int i = blockIdx.x * 1024 + threadIdx.x;   // grid 4 -> exactly NB threads
    float d2  = __uint_as_float(g_key2min[i]);
    float wks = sqrtf(d2);
    g_keyB[i] = wks;

    unsigned b32 = g_row1[i];
    unsigned j  = b32 & 0xFFFu;
    unsigned tw = b32 >> 12;
    unsigned lo = min((unsigned)i, j), hi = max((unsigned)i, j);
    ull kb = ((ull)tw << 26) | ((ull)lo << 13) | hi;

    unsigned tws = __float_as_uint(wks) >> 12;
    ull ksup = ((ull)tws << 26) | ((ull)(unsigned)i << 13) | SUPER;

    g_best[i] = min(kb, ksup);

    ull w = ksup;
    #pragma unroll
    for (int o = 16; o; o >>= 1) w = min(w, __shfl_xor_sync(0xffffffffu, w, o));
    if ((threadIdx.x & 31) == 0) atomicMin(&g_best[SUPER], w);
}

// ---------------- Boruvka scan (rounds >= 2) ----------------
__global__ __launch_bounds__(256) void scan_kernel() {
    if (g_done) return;
    __shared__ __align__(16) int sComp[NN + 3];
    const int tid = threadIdx.x;
    for (int x = tid; x < NN; x += 256) sComp[x] = g_comp[x];
    __syncthreads();

    const int warp = tid >> 5, lane = tid & 31;
    const int i    = blockIdx.x * 8 + warp;
    const int cu   = sComp[i];
    const int csup = sComp[SUPER];

    const uint4* row  = (const uint4*)(g_KEY + (size_t)i * NB);
    const int4*  cmp4 = (const int4*)sComp;

    unsigned best32 = 0xFFFFFFFFu;
    #pragma unroll 8
    for (int c = 0; c < 32; c++) {
        uint4 k  = row[c * 32 + lane];
        int4  cc = cmp4[c * 32 + lane];
        best32 = min(best32, (cc.x == cu) ? 0xFFFFFFFFu : k.x);
        best32 = min(best32, (cc.y == cu) ? 0xFFFFFFFFu : k.y);
        best32 = min(best32, (cc.z == cu) ? 0xFFFFFFFFu : k.z);
        best32 = min(best32, (cc.w == cu) ? 0xFFFFFFFFu : k.w);
    }
    #pragma unroll
    for (int o = 16; o; o >>= 1) best32 = min(best32, __shfl_xor_sync(0xffffffffu, best32, o));

    if (lane == 0) {
        ull kb = ULLMAX;
        if (best32 != 0xFFFFFFFFu) {
            unsigned j  = best32 & 0xFFFu;
            unsigned tw = best32 >> 12;
            unsigned lo = min((unsigned)i, j), hi = max((unsigned)i, j);
            kb = ((ull)tw << 26) | ((ull)lo << 13) | hi;
        }
        if (cu != csup) {
            unsigned tws = __float_as_uint(g_keyB[i]) >> 12;
            ull ks = ((ull)tws << 26) | ((ull)(unsigned)i << 13) | SUPER;
            kb = min(kb, ks);
            atomicMin(&g_best[csup], ks);
        }
        if (kb != ULLMAX) atomicMin(&g_best[cu], kb);
    }
}

// ---------------- merge: select edges, hook, compress (shared mem), accumulate ----------------
__global__ __launch_bounds__(1024) void merge_kernel(const float* __restrict__ P,
                                                     float* __restrict__ out) {
    const int tid = threadIdx.x;
    __shared__ int   sC[NN];
    __shared__ int   sT[NN];
    __shared__ float sRed[32];
    __shared__ int   sCnt[32];

    if (g_done) { if (tid == 0) out[0] = g_total; return; }

    for (int x = tid; x < NN; x += 1024) sC[x] = g_comp[x];
    __syncthreads();

    // A1: snapshot target roots
    for (int x = tid; x < NN; x += 1024) {
        int t = -1;
        if (sC[x] == x) {
            ull k = g_best[x];
            if (k != ULLMAX) {
                int u  = (int)((k >> 13) & 0x1FFFu);
                int v  = (int)(k & 0x1FFFu);
                int c1 = sC[u], c2 = sC[v];
                t = (c1 == x) ? c2 : c1;
            }
        }
        sT[x] = t;
    }
    __syncthreads();

    // A2: count each selected edge once, hook roots (in shared)
    float lsum = 0.f;
    for (int x = tid; x < NN; x += 1024) {
        int t = sT[x];
        if (t >= 0) {
            ull k = g_best[x];
            bool mutual = (g_best[t] == k);
            if (!mutual || x < t) {
                int u = (int)((k >> 13) & 0x1FFFu);
                int v = (int)(k & 0x1FFFu);
                float w;
                if (v == SUPER) {
                    w = g_keyB[u];
                } else {
                    const float* pu = P + (size_t)u * DIMK;
                    const float* pv = P + (size_t)v * DIMK;
                    float s = 0.f;
                    #pragma unroll
                    for (int d = 0; d < DIMK; d++) { float df = pu[d] - pv[d]; s += df * df; }
                    w = sqrtf(s);
                }
                lsum += w;
            }
            if (!(mutual && x < t)) sC[x] = t;
        }
    }
    #pragma unroll
    for (int o = 16; o; o >>= 1) lsum += __shfl_xor_sync(0xffffffffu, lsum, o);
    if ((tid & 31) == 0) sRed[tid >> 5] = lsum;
    __syncthreads();

    // B: pointer jumping fully in shared (double-buffered through registers)
    for (int it = 0; it < 13; it++) {
        int a0 = sC[sC[tid]];
        int a1 = sC[sC[tid + 1024]];
        int a2 = sC[sC[tid + 2048]];
        int a3 = sC[sC[tid + 3072]];
        int a4 = (tid == 0) ? sC[sC[4096]] : 0;
        __syncthreads();
        sC[tid] = a0; sC[tid + 1024] = a1; sC[tid + 2048] = a2; sC[tid + 3072] = a3;
        if (tid == 0) sC[4096] = a4;
        __syncthreads();
    }

    // C: write back, count components, reset bests
    int lcnt = 0;
    for (int x = tid; x < NN; x += 1024) {
        int c = sC[x];
        g_comp[x] = c;
        lcnt += (c == x);
        g_best[x] = ULLMAX;
    }
    #pragma unroll
    for (int o = 16; o; o >>= 1) lcnt += __shfl_xor_sync(0xffffffffu, lcnt, o);
    if ((tid & 31) == 0) sCnt[tid >> 5] = lcnt;
    __syncthreads();

    if (tid == 0) {
        float rs = 0.f; int cnt = 0;
        #pragma unroll
        for (int w = 0; w < 32; w++) { rs += sRed[w]; cnt += sCnt[w]; }
        g_total += rs;
        if (cnt <= 1) g_done = 1;
        out[0] = g_total;
    }
}

// ---------------- launch ----------------
extern "C" void kernel_launch(void* const* d_in, const int* in_sizes, int n_in,
                              void* d_out, int out_size)
{
    const float* batch  = (const float*)d_in[0];   // [16384,128]
    const float* output = (const float*)d_in[1];   // [4096,128]
    float* out = (float*)d_out;

    sqnorm_kernel<<<(NA + NB) / 8, 256>>>(batch, output);
    init_kernel<<<16, 1024>>>();

    dim3 g2(NB / 64, NA / 512);
    key_init_kernel<<<g2, 256>>>(output, batch);

    dim3 g3(NB / 64, NB / 64);
    dbb_kernel<<<g3, 256>>>(output);

    round1_kernel<<<NB / 1024, 1024>>>();
    merge_kernel<<<1, 1024>>>(output, out);

    for (int r = 0; r < 12; r++) {
        scan_kernel<<<NB / 8, 256>>>();
        merge_kernel<<<1, 1024>>>(output, out);
    }
}

// round 5
// speedup vs baseline: 7.8314x; 1.2152x over previous
#include <cuda_runtime.h>
#include <cuda_bf16.h>
#include <math_constants.h>

#define NA    4096
#define NB    4096
#define DIMK  128
#define NN    4097
#define SUPER 4096
#define ULLMAX 0xFFFFFFFFFFFFFFFFULL

typedef unsigned long long ull;

// swizzled column for [k][row128] smem tiles (banks spread by k-group)
#define SWZ(k, c) ((c) ^ ((((k) >> 2) & 7) << 2))

// ---------------- scratch ----------------
__device__ __align__(16) float    g_sqA[NA];
__device__ __align__(16) float    g_sqB[NB];
__device__ __align__(16) float    g_keyB[NB];      // sqrt(min d^2 to A)  (weights only)
__device__ __align__(16) unsigned g_key2min[NB];   // fp32 bits of min clamped d^2 (B->A)
__device__ __align__(16) unsigned g_row1[NB];      // round-1 per-row min packed key (d^2 based)
__device__ __align__(16) unsigned g_KEY[(size_t)NB * NB];  // 64MB packed (d2w20|col12)
__device__ int  g_comp[NN];
__device__ ull  g_best[NN];
__device__ float g_total;
__device__ int   g_done;

// ---------------- K1: squared norms ----------------
__global__ __launch_bounds__(256) void sqnorm_kernel(const float* __restrict__ batch,
                                                     const float* __restrict__ output) {
    int row  = blockIdx.x * 8 + (threadIdx.x >> 5);
    int lane = threadIdx.x & 31;
    const float* src = (row < NA) ? (batch + (size_t)row * DIMK)
                                  : (output + (size_t)(row - NA) * DIMK);
    float s = 0.f;
    #pragma unroll
    for (int k = lane; k < DIMK; k += 32) { float v = src[k]; s += v * v; }
    #pragma unroll
    for (int o = 16; o; o >>= 1) s += __shfl_down_sync(0xffffffffu, s, o);
    if (lane == 0) {
        if (row < NA) g_sqA[row] = s;
        else          g_sqB[row - NA] = s;
    }
}

// ---------------- init ----------------
__global__ __launch_bounds__(1024) void init_kernel() {
    int i = blockIdx.x * blockDim.x + threadIdx.x;
    int stride = gridDim.x * blockDim.x;
    for (int x = i; x < NN; x += stride) { g_comp[x] = x; g_best[x] = ULLMAX; }
    for (int x = i; x < NB; x += stride) { g_row1[x] = 0xFFFFFFFFu; g_key2min[x] = 0x7F800000u; }
    if (i == 0) { g_total = 0.f; g_done = 0; }
}

// ---------------- chunk loader: [32 k][128 rows] transposed + swizzle ----------------
__device__ __forceinline__ void load_chunk(float* st, const float* __restrict__ g, int kc) {
    int tid = threadIdx.x;
    #pragma unroll
    for (int it = 0; it < 4; it++) {
        int f  = tid + it * 256;
        int r  = f >> 3;              // row 0..127
        int kq = (f & 7) << 2;        // k within chunk, float4 aligned
        float4 v = *(const float4*)(g + (size_t)r * DIMK + kc * 32 + kq);
        int c = SWZ(kq, r);
        st[(kq + 0) * 128 + c] = v.x;
        st[(kq + 1) * 128 + c] = v.y;
        st[(kq + 2) * 128 + c] = v.z;
        st[(kq + 3) * 128 + c] = v.w;
    }
}

// 8x8 register-tile GEMM over a 32-k chunk
__device__ __forceinline__ void gemm32(const float* sP, const float* sQ,
                                       float acc[8][8], int tx, int ty) {
    #pragma unroll
    for (int kl = 0; kl < 32; kl++) {
        float p[8], q[8];
        *(float4*)&p[0] = *(const float4*)&sP[kl * 128 + SWZ(kl, ty * 4)];
        *(float4*)&p[4] = *(const float4*)&sP[kl * 128 + SWZ(kl, 64 + ty * 4)];
        *(float4*)&q[0] = *(const float4*)&sQ[kl * 128 + SWZ(kl, tx * 4)];
        *(float4*)&q[4] = *(const float4*)&sQ[kl * 128 + SWZ(kl, 64 + tx * 4)];
        #pragma unroll
        for (int i = 0; i < 8; i++)
            #pragma unroll
            for (int j = 0; j < 8; j++) acc[i][j] += p[i] * q[j];
    }
}

// ---------------- K2: min_a d^2(b,a) -> g_key2min ----------------
__global__ __launch_bounds__(256) void key_init_kernel(const float* __restrict__ P,  // B
                                                       const float* __restrict__ Q)  // A
{
    __shared__ __align__(16) float sP[32 * 128];
    __shared__ __align__(16) float sQ[32 * 128];
    const int tid = threadIdx.x, tx = tid & 15, ty = tid >> 4;
    const int m0 = blockIdx.x * 128;
    const int a0 = blockIdx.y * 512;

    float minv[8] = {CUDART_INF_F, CUDART_INF_F, CUDART_INF_F, CUDART_INF_F,
                     CUDART_INF_F, CUDART_INF_F, CUDART_INF_F, CUDART_INF_F};

    for (int t = 0; t < 4; t++) {
        int n0 = a0 + t * 128;
        float acc[8][8] = {};
        for (int kc = 0; kc < 4; kc++) {
            __syncthreads();
            load_chunk(sP, P + (size_t)m0 * DIMK, kc);
            load_chunk(sQ, Q + (size_t)n0 * DIMK, kc);
            __syncthreads();
            gemm32(sP, sQ, acc, tx, ty);
        }
        #pragma unroll
        for (int rj = 0; rj < 8; rj++) {
            int lj = (rj < 4) ? tx * 4 + rj : 64 + tx * 4 + (rj - 4);
            float sqa = g_sqA[n0 + lj];
            #pragma unroll
            for (int ri = 0; ri < 8; ri++)
                minv[ri] = fminf(minv[ri], sqa - 2.f * acc[ri][rj]);
        }
    }
    #pragma unroll
    for (int ri = 0; ri < 8; ri++) {
        float m = minv[ri];
        #pragma unroll
        for (int o = 8; o; o >>= 1) m = fminf(m, __shfl_xor_sync(0xffffffffu, m, o));
        if (tx == 0) {
            int li = (ri < 4) ? ty * 4 + ri : 64 + ty * 4 + (ri - 4);
            int row = m0 + li;
            float v = fmaxf(g_sqB[row] + m, 0.f);
            atomicMin(&g_key2min[row], __float_as_uint(v));
        }
    }
}

// ---------------- K3: packed d^2 key matrix (symmetric, upper blocks only) ----------------
__global__ __launch_bounds__(256) void dbb_kernel(const float* __restrict__ P)
{
    const int bx = blockIdx.x, by = blockIdx.y;
    if (bx < by) return;
    __shared__ __align__(16) float sP[32 * 128];
    __shared__ __align__(16) float sQ[32 * 128];
    __shared__ unsigned sRowMin[128];
    __shared__ unsigned sColMin[128];

    const int tid = threadIdx.x, tx = tid & 15, ty = tid >> 4;
    const int m0 = by * 128, n0 = bx * 128;

    float acc[8][8] = {};
    for (int kc = 0; kc < 4; kc++) {
        __syncthreads();
        load_chunk(sP, P + (size_t)m0 * DIMK, kc);
        load_chunk(sQ, P + (size_t)n0 * DIMK, kc);
        __syncthreads();
        gemm32(sP, sQ, acc, tx, ty);
    }
    if (tid < 128) { sRowMin[tid] = 0xFFFFFFFFu; sColMin[tid] = 0xFFFFFFFFu; }
    __syncthreads();

    float sqi[8], sqj[8];
    #pragma unroll
    for (int r = 0; r < 8; r++) {
        int li = (r < 4) ? ty * 4 + r : 64 + ty * 4 + (r - 4);
        int lj = (r < 4) ? tx * 4 + r : 64 + tx * 4 + (r - 4);
        sqi[r] = g_sqB[m0 + li];
        sqj[r] = g_sqB[n0 + lj];
    }

    // normal orientation: rows bi, cols bj
    unsigned cmin[8] = {0xFFFFFFFFu, 0xFFFFFFFFu, 0xFFFFFFFFu, 0xFFFFFFFFu,
                        0xFFFFFFFFu, 0xFFFFFFFFu, 0xFFFFFFFFu, 0xFFFFFFFFu};
    #pragma unroll
    for (int ri = 0; ri < 8; ri++) {
        int li = (ri < 4) ? ty * 4 + ri : 64 + ty * 4 + (ri - 4);
        int bi = m0 + li;
        unsigned pk[8];
        unsigned rmin = 0xFFFFFFFFu;
        #pragma unroll
        for (int rj = 0; rj < 8; rj++) {
            int lj = (rj < 4) ? tx * 4 + rj : 64 + tx * 4 + (rj - 4);
            int bj = n0 + lj;
            float d2 = fmaxf(sqi[ri] + sqj[rj] - 2.f * acc[ri][rj], 0.f);
            unsigned pb = __float_as_uint(d2) & 0xFFFFF000u;
            pk[rj] = pb | (unsigned)bj;
            if (bi != bj) {
                rmin     = min(rmin, pk[rj]);
                cmin[rj] = min(cmin[rj], pb | (unsigned)bi);
            }
        }
        *(uint4*)&g_KEY[(size_t)bi * NB + n0 + tx * 4]      = make_uint4(pk[0], pk[1], pk[2], pk[3]);
        *(uint4*)&g_KEY[(size_t)bi * NB + n0 + 64 + tx * 4] = make_uint4(pk[4], pk[5], pk[6], pk[7]);
        atomicMin(&sRowMin[li], rmin);
    }

    // transposed tile (only strictly-upper blocks)
    if (bx > by) {
        #pragma unroll
        for (int rj = 0; rj < 8; rj++) {
            int lj = (rj < 4) ? tx * 4 + rj : 64 + tx * 4 + (rj - 4);
            int bj = n0 + lj;
            unsigned tk[8];
            #pragma unroll
            for (int ri = 0; ri < 8; ri++) {
                int li = (ri < 4) ? ty * 4 + ri : 64 + ty * 4 + (ri - 4);
                int bi = m0 + li;
                float d2 = fmaxf(sqi[ri] + sqj[rj] - 2.f * acc[ri][rj], 0.f);
                tk[ri] = (__float_as_uint(d2) & 0xFFFFF000u) | (unsigned)bi;
            }
            *(uint4*)&g_KEY[(size_t)bj * NB + m0 + ty * 4]      = make_uint4(tk[0], tk[1], tk[2], tk[3]);
            *(uint4*)&g_KEY[(size_t)bj * NB + m0 + 64 + ty * 4] = make_uint4(tk[4], tk[5], tk[6], tk[7]);
            atomicMin(&sColMin[lj], cmin[rj]);
        }
    }
    __syncthreads();
    if (tid < 128) {
        atomicMin(&g_row1[m0 + tid], sRowMin[tid]);
        if (bx > by) atomicMin(&g_row1[n0 + tid], sColMin[tid]);
    }
}

// ---------------- round-1 best assembly (replaces first scan) ----------------
__global__ __launch_bounds__(1024) void round1_kernel() {
    int i = blockIdx.x * 1024 + threadIdx.x;
    unsigned d2b = g_key2min[i];
    g_keyB[i] = sqrtf(__uint_as_float(d2b));

    unsigned b32 = g_row1[i];
    unsigned j  = b32 & 0xFFFu;
    unsigned tw = b32 >> 12;
    unsigned lo = min((unsigned)i, j), hi = max((unsigned)i, j);
    ull kb = ((ull)tw << 26) | ((ull)lo << 13) | hi;

    unsigned tws = d2b >> 12;
    ull ksup = ((ull)tws << 26) | ((ull)(unsigned)i << 13) | SUPER;

    g_best[i] = min(kb, ksup);

    ull w = ksup;
    #pragma unroll
    for (int o = 16; o; o >>= 1) w = min(w, __shfl_xor_sync(0xffffffffu, w, o));
    if ((threadIdx.x & 31) == 0) atomicMin(&g_best[SUPER], w);
}

// ---------------- Boruvka scan (rounds >= 2) ----------------
__global__ __launch_bounds__(256) void scan_kernel() {
    if (g_done) return;
    __shared__ __align__(16) int sComp[NN + 3];
    const int tid = threadIdx.x;
    for (int x = tid; x < NN; x += 256) sComp[x] = g_comp[x];
    __syncthreads();

    const int warp = tid >> 5, lane = tid & 31;
    const int i    = blockIdx.x * 8 + warp;
    const int cu   = sComp[i];
    const int csup = sComp[SUPER];

    const uint4* row  = (const uint4*)(g_KEY + (size_t)i * NB);
    const int4*  cmp4 = (const int4*)sComp;

    unsigned best32 = 0xFFFFFFFFu;
    #pragma unroll 8
    for (int c = 0; c < 32; c++) {
        uint4 k  = row[c * 32 + lane];
        int4  cc = cmp4[c * 32 + lane];
        if (cc.x != cu) best32 = min(best32, k.x);
        if (cc.y != cu) best32 = min(best32, k.y);
        if (cc.z != cu) best32 = min(best32, k.z);
        if (cc.w != cu) best32 = min(best32, k.w);
    }
    #pragma unroll
    for (int o = 16; o; o >>= 1) best32 = min(best32, __shfl_xor_sync(0xffffffffu, best32, o));

    if (lane == 0) {
        ull kb = ULLMAX;
        if (best32 != 0xFFFFFFFFu) {
            unsigned j  = best32 & 0xFFFu;
            unsigned tw = best32 >> 12;
            unsigned lo = min((unsigned)i, j), hi = max((unsigned)i, j);
            kb = ((ull)tw << 26) | ((ull)lo << 13) | hi;
        }
        if (cu != csup) {
            unsigned tws = g_key2min[i] >> 12;
            ull ks = ((ull)tws << 26) | ((ull)(unsigned)i << 13) | SUPER;
            kb = min(kb, ks);
            atomicMin(&g_best[csup], ks);
        }
        if (kb != ULLMAX) atomicMin(&g_best[cu], kb);
    }
}

// ---------------- merge ----------------
__global__ __launch_bounds__(1024) void merge_kernel(const float* __restrict__ P,
                                                     float* __restrict__ out) {
    const int tid = threadIdx.x;
    __shared__ int   sC[NN];
    __shared__ int   sT[NN];
    __shared__ float sRed[32];
    __shared__ int   sCnt[32];

    if (g_done) { if (tid == 0) out[0] = g_total; return; }

    for (int x = tid; x < NN; x += 1024) sC[x] = g_comp[x];
    __syncthreads();

    for (int x = tid; x < NN; x += 1024) {
        int t = -1;
        if (sC[x] == x) {
            ull k = g_best[x];
            if (k != ULLMAX) {
                int u  = (int)((k >> 13) & 0x1FFFu);
                int v  = (int)(k & 0x1FFFu);
                int c1 = sC[u], c2 = sC[v];
                t = (c1 == x) ? c2 : c1;
            }
        }
        sT[x] = t;
    }
    __syncthreads();

    float lsum = 0.f;
    for (int x = tid; x < NN; x += 1024) {
        int t = sT[x];
        if (t >= 0) {
            ull k = g_best[x];
            bool mutual = (g_best[t] == k);
            if (!mutual || x < t) {
                int u = (int)((k >> 13) & 0x1FFFu);
                int v = (int)(k & 0x1FFFu);
                float w;
                if (v == SUPER) {
                    w = g_keyB[u];
                } else {
                    const float* pu = P + (size_t)u * DIMK;
                    const float* pv = P + (size_t)v * DIMK;
                    float s = 0.f;
                    #pragma unroll
                    for (int d = 0; d < DIMK; d++) { float df = pu[d] - pv[d]; s += df * df; }
                    w = sqrtf(s);
                }
                lsum += w;
            }
            if (!(mutual && x < t)) sC[x] = t;
        }
    }
    #pragma unroll
    for (int o = 16; o; o >>= 1) lsum += __shfl_xor_sync(0xffffffffu, lsum, o);
    if ((tid & 31) == 0) sRed[tid >> 5] = lsum;
    __syncthreads();

    for (int it = 0; it < 13; it++) {
        int a0 = sC[sC[tid]];
        int a1 = sC[sC[tid + 1024]];
        int a2 = sC[sC[tid + 2048]];
        int a3 = sC[sC[tid + 3072]];
        int a4 = (tid == 0) ? sC[sC[4096]] : 0;
        __syncthreads();
        sC[tid] = a0; sC[tid + 1024] = a1; sC[tid + 2048] = a2; sC[tid + 3072] = a3;
        if (tid == 0) sC[4096] = a4;
        __syncthreads();
    }

    int lcnt = 0;
    for (int x = tid; x < NN; x += 1024) {
        int c = sC[x];
        g_comp[x] = c;
        lcnt += (c == x);
        g_best[x] = ULLMAX;
    }
    #pragma unroll
    for (int o = 16; o; o >>= 1) lcnt += __shfl_xor_sync(0xffffffffu, lcnt, o);
    if ((tid & 31) == 0) sCnt[tid >> 5] = lcnt;
    __syncthreads();

    if (tid == 0) {
        float rs = 0.f; int cnt = 0;
        #pragma unroll
        for (int w = 0; w < 32; w++) { rs += sRed[w]; cnt += sCnt[w]; }
        g_total += rs;
        if (cnt <= 1) g_done = 1;
        out[0] = g_total;
    }
}

// ---------------- launch ----------------
extern "C" void kernel_launch(void* const* d_in, const int* in_sizes, int n_in,
                              void* d_out, int out_size)
{
    const float* batch  = (const float*)d_in[0];   // [16384,128]
    const float* output = (const float*)d_in[1];   // [4096,128]
    float* out = (float*)d_out;

    sqnorm_kernel<<<(NA + NB) / 8, 256>>>(batch, output);
    init_kernel<<<16, 1024>>>();

    dim3 g2(NB / 128, NA / 512);
    key_init_kernel<<<g2, 256>>>(output, batch);

    dim3 g3(NB / 128, NB / 128);
    dbb_kernel<<<g3, 256>>>(output);

    round1_kernel<<<NB / 1024, 1024>>>();
    merge_kernel<<<1, 1024>>>(output, out);

    for (int r = 0; r < 12; r++) {
        scan_kernel<<<NB / 8, 256>>>();
        merge_kernel<<<1, 1024>>>(output, out);
    }
}

// round 6
// speedup vs baseline: 8.4248x; 1.0758x over previous
#include <cuda_runtime.h>
#include <cuda_bf16.h>
#include <math_constants.h>

#define NA    4096
#define NB    4096
#define DIMK  128
#define NN    4097
#define SUPER 4096
#define ULLMAX 0xFFFFFFFFFFFFFFFFULL

typedef unsigned long long ull;

// swizzled column for [k][row128] smem tiles
#define SWZ(k, c) ((c) ^ ((((k) >> 2) & 7) << 2))

// ---------------- scratch ----------------
__device__ __align__(16) float    g_sqA[NA];
__device__ __align__(16) float    g_sqB[NB];
__device__ __align__(16) float    g_keyB[NB];      // exact sqrt(d^2(b, a*))
__device__ __align__(16) unsigned g_key2min[NB];   // exact fp32 bits of d^2(b, a*)
__device__ __align__(16) unsigned g_amin[NB];      // packed (approx d2 | a idx)
__device__ __align__(16) unsigned g_row1[NB];      // round-1 per-row min packed key
__device__ __align__(16) unsigned g_Abf[NA * 64];  // bf16x2 packed A points
__device__ __align__(16) unsigned g_Bbf[NB * 64];  // bf16x2 packed B points
__device__ __align__(16) unsigned g_KEY[(size_t)NB * NB];  // 64MB packed (d2w20|col12)
__device__ int  g_comp[NN];
__device__ ull  g_best[NN];
__device__ float g_total;
__device__ int   g_done;

__device__ __forceinline__ __nv_bfloat162 bf2(unsigned& x) {
    return *reinterpret_cast<__nv_bfloat162*>(&x);
}

// ---------------- K1: squared norms (exact fp32) ----------------
__global__ __launch_bounds__(256) void sqnorm_kernel(const float* __restrict__ batch,
                                                     const float* __restrict__ output) {
    int row  = blockIdx.x * 8 + (threadIdx.x >> 5);
    int lane = threadIdx.x & 31;
    const float* src = (row < NA) ? (batch + (size_t)row * DIMK)
                                  : (output + (size_t)(row - NA) * DIMK);
    float s = 0.f;
    #pragma unroll
    for (int k = lane; k < DIMK; k += 32) { float v = src[k]; s += v * v; }
    #pragma unroll
    for (int o = 16; o; o >>= 1) s += __shfl_down_sync(0xffffffffu, s, o);
    if (lane == 0) {
        if (row < NA) g_sqA[row] = s;
        else          g_sqB[row - NA] = s;
    }
}

// ---------------- convert to bf16x2 ----------------
__global__ __launch_bounds__(256) void tobf_kernel(const float* __restrict__ batch,
                                                   const float* __restrict__ output) {
    int idx = blockIdx.x * 256 + threadIdx.x;   // 0 .. 8192*64
    int row = idx >> 6, c = idx & 63;
    const float* src = (row < NA) ? (batch + (size_t)row * DIMK)
                                  : (output + (size_t)(row - NA) * DIMK);
    float2 v = *(const float2*)(src + c * 2);
    __nv_bfloat162 b = __float22bfloat162_rn(v);
    unsigned bits = *reinterpret_cast<unsigned*>(&b);
    if (row < NA) g_Abf[row * 64 + c] = bits;
    else          g_Bbf[(row - NA) * 64 + c] = bits;
}

// ---------------- init ----------------
__global__ __launch_bounds__(1024) void init_kernel() {
    int i = blockIdx.x * blockDim.x + threadIdx.x;
    int stride = gridDim.x * blockDim.x;
    for (int x = i; x < NN; x += stride) { g_comp[x] = x; g_best[x] = ULLMAX; }
    for (int x = i; x < NB; x += stride) { g_row1[x] = 0xFFFFFFFFu; g_amin[x] = 0xFFFFFFFFu; }
    if (i == 0) { g_total = 0.f; g_done = 0; }
}

// ---------------- bf16x2 chunk loader: [32 kpair][128 rows] + swizzle ----------------
__device__ __forceinline__ void load_chunk_bf(unsigned* st, const unsigned* __restrict__ g, int kc) {
    int tid = threadIdx.x;
    #pragma unroll
    for (int it = 0; it < 4; it++) {
        int f  = tid + it * 256;
        int r  = f >> 3;              // row 0..127
        int kq = (f & 7) << 2;        // kpair 0..28 step 4
        uint4 v = *(const uint4*)(g + (size_t)r * 64 + kc * 32 + kq);
        int c = SWZ(kq, r);
        st[(kq + 0) * 128 + c] = v.x;
        st[(kq + 1) * 128 + c] = v.y;
        st[(kq + 2) * 128 + c] = v.z;
        st[(kq + 3) * 128 + c] = v.w;
    }
}

// 8x8 register-tile bf16x2 GEMM over a 32-kpair chunk (HFMA2: 2 MACs/instr)
__device__ __forceinline__ void gemm32_bf(const unsigned* sP, const unsigned* sQ,
                                          __nv_bfloat162 acc[8][8], int tx, int ty) {
    #pragma unroll
    for (int kl = 0; kl < 32; kl++) {
        unsigned p[8], q[8];
        *(uint4*)&p[0] = *(const uint4*)&sP[kl * 128 + SWZ(kl, ty * 4)];
        *(uint4*)&p[4] = *(const uint4*)&sP[kl * 128 + SWZ(kl, 64 + ty * 4)];
        *(uint4*)&q[0] = *(const uint4*)&sQ[kl * 128 + SWZ(kl, tx * 4)];
        *(uint4*)&q[4] = *(const uint4*)&sQ[kl * 128 + SWZ(kl, 64 + tx * 4)];
        #pragma unroll
        for (int i = 0; i < 8; i++)
            #pragma unroll
            for (int j = 0; j < 8; j++)
                acc[i][j] = __hfma2(bf2(p[i]), bf2(q[j]), acc[i][j]);
    }
}

__device__ __forceinline__ float dotf(__nv_bfloat162 a) {
    return __low2float(a) + __high2float(a);
}

// ---------------- K2: approx argmin_a d^2(b,a) -> g_amin (packed d2|aidx) ----------------
__global__ __launch_bounds__(256, 2) void key_init_kernel()
{
    __shared__ __align__(16) unsigned sP[32 * 128];
    __shared__ __align__(16) unsigned sQ[32 * 128];
    const int tid = threadIdx.x, tx = tid & 15, ty = tid >> 4;
    const int m0 = blockIdx.x * 128;
    const int a0 = blockIdx.y * 512;

    float sqb[8];
    #pragma unroll
    for (int r = 0; r < 8; r++) {
        int li = (r < 4) ? ty * 4 + r : 64 + ty * 4 + (r - 4);
        sqb[r] = g_sqB[m0 + li];
    }

    unsigned umin[8] = {0xFFFFFFFFu, 0xFFFFFFFFu, 0xFFFFFFFFu, 0xFFFFFFFFu,
                        0xFFFFFFFFu, 0xFFFFFFFFu, 0xFFFFFFFFu, 0xFFFFFFFFu};

    for (int t = 0; t < 4; t++) {
        int n0 = a0 + t * 128;
        __nv_bfloat162 zz = __float2bfloat162_rn(0.f);
        __nv_bfloat162 acc[8][8];
        #pragma unroll
        for (int i = 0; i < 8; i++)
            #pragma unroll
            for (int j = 0; j < 8; j++) acc[i][j] = zz;
        for (int kc = 0; kc < 2; kc++) {
            __syncthreads();
            load_chunk_bf(sP, g_Bbf + (size_t)m0 * 64, kc);
            load_chunk_bf(sQ, g_Abf + (size_t)n0 * 64, kc);
            __syncthreads();
            gemm32_bf(sP, sQ, acc, tx, ty);
        }
        #pragma unroll
        for (int rj = 0; rj < 8; rj++) {
            int lj = (rj < 4) ? tx * 4 + rj : 64 + tx * 4 + (rj - 4);
            int aj = n0 + lj;
            float sqa = g_sqA[aj];
            #pragma unroll
            for (int ri = 0; ri < 8; ri++) {
                float d2 = fmaxf(sqb[ri] + sqa - 2.f * dotf(acc[ri][rj]), 0.f);
                unsigned pk = (__float_as_uint(d2) & 0xFFFFF000u) | (unsigned)aj;
                umin[ri] = min(umin[ri], pk);
            }
        }
    }
    #pragma unroll
    for (int ri = 0; ri < 8; ri++) {
        unsigned m = umin[ri];
        #pragma unroll
        for (int o = 8; o; o >>= 1) m = min(m, __shfl_xor_sync(0xffffffffu, m, o));
        if (tx == 0) {
            int li = (ri < 4) ? ty * 4 + ri : 64 + ty * 4 + (ri - 4);
            atomicMin(&g_amin[m0 + li], m);
        }
    }
}

// ---------------- K3: packed approx-d^2 key matrix (symmetric, upper blocks) ----------------
__global__ __launch_bounds__(256, 2) void dbb_kernel()
{
    const int bx = blockIdx.x, by = blockIdx.y;
    if (bx < by) return;
    __shared__ __align__(16) unsigned sP[32 * 128];
    __shared__ __align__(16) unsigned sQ[32 * 128];
    __shared__ unsigned sRowMin[128];
    __shared__ unsigned sColMin[128];

    const int tid = threadIdx.x, tx = tid & 15, ty = tid >> 4;
    const int m0 = by * 128, n0 = bx * 128;

    __nv_bfloat162 zz = __float2bfloat162_rn(0.f);
    __nv_bfloat162 acc[8][8];
    #pragma unroll
    for (int i = 0; i < 8; i++)
        #pragma unroll
        for (int j = 0; j < 8; j++) acc[i][j] = zz;
    for (int kc = 0; kc < 2; kc++) {
        __syncthreads();
        load_chunk_bf(sP, g_Bbf + (size_t)m0 * 64, kc);
        load_chunk_bf(sQ, g_Bbf + (size_t)n0 * 64, kc);
        __syncthreads();
        gemm32_bf(sP, sQ, acc, tx, ty);
    }
    if (tid < 128) { sRowMin[tid] = 0xFFFFFFFFu; sColMin[tid] = 0xFFFFFFFFu; }
    __syncthreads();

    float sqi[8], sqj[8];
    #pragma unroll
    for (int r = 0; r < 8; r++) {
        int li = (r < 4) ? ty * 4 + r : 64 + ty * 4 + (r - 4);
        int lj = (r < 4) ? tx * 4 + r : 64 + tx * 4 + (r - 4);
        sqi[r] = g_sqB[m0 + li];
        sqj[r] = g_sqB[n0 + lj];
    }

    unsigned cmin[8] = {0xFFFFFFFFu, 0xFFFFFFFFu, 0xFFFFFFFFu, 0xFFFFFFFFu,
                        0xFFFFFFFFu, 0xFFFFFFFFu, 0xFFFFFFFFu, 0xFFFFFFFFu};
    #pragma unroll
    for (int ri = 0; ri < 8; ri++) {
        int li = (ri < 4) ? ty * 4 + ri : 64 + ty * 4 + (ri - 4);
        int bi = m0 + li;
        unsigned pk[8];
        unsigned rmin = 0xFFFFFFFFu;
        #pragma unroll
        for (int rj = 0; rj < 8; rj++) {
            int lj = (rj < 4) ? tx * 4 + rj : 64 + tx * 4 + (rj - 4);
            int bj = n0 + lj;
            float d2 = fmaxf(sqi[ri] + sqj[rj] - 2.f * dotf(acc[ri][rj]), 0.f);
            unsigned pb = __float_as_uint(d2) & 0xFFFFF000u;
            pk[rj] = pb | (unsigned)bj;
            if (bi != bj) {
                rmin     = min(rmin, pk[rj]);
                cmin[rj] = min(cmin[rj], pb | (unsigned)bi);
            }
        }
        *(uint4*)&g_KEY[(size_t)bi * NB + n0 + tx * 4]      = make_uint4(pk[0], pk[1], pk[2], pk[3]);
        *(uint4*)&g_KEY[(size_t)bi * NB + n0 + 64 + tx * 4] = make_uint4(pk[4], pk[5], pk[6], pk[7]);
        atomicMin(&sRowMin[li], rmin);
    }

    if (bx > by) {
        #pragma unroll
        for (int rj = 0; rj < 8; rj++) {
            int lj = (rj < 4) ? tx * 4 + rj : 64 + tx * 4 + (rj - 4);
            int bj = n0 + lj;
            unsigned tk[8];
            #pragma unroll
            for (int ri = 0; ri < 8; ri++) {
                int li = (ri < 4) ? ty * 4 + ri : 64 + ty * 4 + (ri - 4);
                int bi = m0 + li;
                float d2 = fmaxf(sqi[ri] + sqj[rj] - 2.f * dotf(acc[ri][rj]), 0.f);
                tk[ri] = (__float_as_uint(d2) & 0xFFFFF000u) | (unsigned)bi;
            }
            *(uint4*)&g_KEY[(size_t)bj * NB + m0 + ty * 4]      = make_uint4(tk[0], tk[1], tk[2], tk[3]);
            *(uint4*)&g_KEY[(size_t)bj * NB + m0 + 64 + ty * 4] = make_uint4(tk[4], tk[5], tk[6], tk[7]);
            atomicMin(&sColMin[lj], cmin[rj]);
        }
    }
    __syncthreads();
    if (tid < 128) {
        atomicMin(&g_row1[m0 + tid], sRowMin[tid]);
        if (bx > by) atomicMin(&g_row1[n0 + tid], sColMin[tid]);
    }
}

// ---------------- round 1: exact keyB repair + best assembly ----------------
__global__ __launch_bounds__(256) void round1_kernel(const float* __restrict__ batch,
                                                     const float* __restrict__ output) {
    int i = blockIdx.x * 256 + threadIdx.x;     // grid 16 -> NB threads
    int a = (int)(g_amin[i] & 0xFFFu);

    // exact fp32 d^2(b_i, a)
    const float4* pb = (const float4*)(output + (size_t)i * DIMK);
    const float4* pa = (const float4*)(batch  + (size_t)a * DIMK);
    float s = 0.f;
    #pragma unroll
    for (int q = 0; q < 32; q++) {
        float4 vb = pb[q], va = pa[q];
        float dx = vb.x - va.x, dy = vb.y - va.y, dz = vb.z - va.z, dw = vb.w - va.w;
        s += dx * dx + dy * dy + dz * dz + dw * dw;
    }
    unsigned d2b = __float_as_uint(s);
    g_key2min[i] = d2b;
    g_keyB[i]    = sqrtf(s);

    unsigned b32 = g_row1[i];
    unsigned j  = b32 & 0xFFFu;
    unsigned tw = b32 >> 12;
    unsigned lo = min((unsigned)i, j), hi = max((unsigned)i, j);
    ull kb = ((ull)tw << 26) | ((ull)lo << 13) | hi;

    unsigned tws = d2b >> 12;
    ull ksup = ((ull)tws << 26) | ((ull)(unsigned)i << 13) | SUPER;

    g_best[i] = min(kb, ksup);

    ull w = ksup;
    #pragma unroll
    for (int o = 16; o; o >>= 1) w = min(w, __shfl_xor_sync(0xffffffffu, w, o));
    if ((threadIdx.x & 31) == 0) atomicMin(&g_best[SUPER], w);
}

// ---------------- Boruvka scan (rounds >= 2) ----------------
__global__ __launch_bounds__(256) void scan_kernel() {
    if (g_done) return;
    __shared__ __align__(16) int sComp[NN + 3];
    const int tid = threadIdx.x;
    for (int x = tid; x < NN; x += 256) sComp[x] = g_comp[x];
    __syncthreads();

    const int warp = tid >> 5, lane = tid & 31;
    const int i    = blockIdx.x * 8 + warp;
    const int cu   = sComp[i];
    const int csup = sComp[SUPER];

    const uint4* row  = (const uint4*)(g_KEY + (size_t)i * NB);
    const int4*  cmp4 = (const int4*)sComp;

    unsigned best32 = 0xFFFFFFFFu;
    #pragma unroll 8
    for (int c = 0; c < 32; c++) {
        uint4 k  = row[c * 32 + lane];
        int4  cc = cmp4[c * 32 + lane];
        if (cc.x != cu) best32 = min(best32, k.x);
        if (cc.y != cu) best32 = min(best32, k.y);
        if (cc.z != cu) best32 = min(best32, k.z);
        if (cc.w != cu) best32 = min(best32, k.w);
    }
    #pragma unroll
    for (int o = 16; o; o >>= 1) best32 = min(best32, __shfl_xor_sync(0xffffffffu, best32, o));

    if (lane == 0) {
        ull kb = ULLMAX;
        if (best32 != 0xFFFFFFFFu) {
            unsigned j  = best32 & 0xFFFu;
            unsigned tw = best32 >> 12;
            unsigned lo = min((unsigned)i, j), hi = max((unsigned)i, j);
            kb = ((ull)tw << 26) | ((ull)lo << 13) | hi;
        }
        if (cu != csup) {
            unsigned tws = g_key2min[i] >> 12;
            ull ks = ((ull)tws << 26) | ((ull)(unsigned)i << 13) | SUPER;
            kb = min(kb, ks);
            atomicMin(&g_best[csup], ks);
        }
        if (kb != ULLMAX) atomicMin(&g_best[cu], kb);
    }
}

// ---------------- merge (exact fp32 weights) ----------------
__global__ __launch_bounds__(1024) void merge_kernel(const float* __restrict__ P,
                                                     float* __restrict__ out) {
    const int tid = threadIdx.x;
    __shared__ int   sC[NN];
    __shared__ int   sT[NN];
    __shared__ float sRed[32];
    __shared__ int   sCnt[32];

    if (g_done) { if (tid == 0) out[0] = g_total; return; }

    for (int x = tid; x < NN; x += 1024) sC[x] = g_comp[x];
    __syncthreads();

    for (int x = tid; x < NN; x += 1024) {
        int t = -1;
        if (sC[x] == x) {
            ull k = g_best[x];
            if (k != ULLMAX) {
                int u  = (int)((k >> 13) & 0x1FFFu);
                int v  = (int)(k & 0x1FFFu);
                int c1 = sC[u], c2 = sC[v];
                t = (c1 == x) ? c2 : c1;
            }
        }
        sT[x] = t;
    }
    __syncthreads();

    float lsum = 0.f;
    for (int x = tid; x < NN; x += 1024) {
        int t = sT[x];
        if (t >= 0) {
            ull k = g_best[x];
            bool mutual = (g_best[t] == k);
            if (!mutual || x < t) {
                int u = (int)((k >> 13) & 0x1FFFu);
                int v = (int)(k & 0x1FFFu);
                float w;
                if (v == SUPER) {
                    w = g_keyB[u];
                } else {
                    const float* pu = P + (size_t)u * DIMK;
                    const float* pv = P + (size_t)v * DIMK;
                    float s = 0.f;
                    #pragma unroll
                    for (int d = 0; d < DIMK; d++) { float df = pu[d] - pv[d]; s += df * df; }
                    w = sqrtf(s);
                }
                lsum += w;
            }
            if (!(mutual && x < t)) sC[x] = t;
        }
    }
    #pragma unroll
    for (int o = 16; o; o >>= 1) lsum += __shfl_xor_sync(0xffffffffu, lsum, o);
    if ((tid & 31) == 0) sRed[tid >> 5] = lsum;
    __syncthreads();

    for (int it = 0; it < 13; it++) {
        int a0 = sC[sC[tid]];
        int a1 = sC[sC[tid + 1024]];
        int a2 = sC[sC[tid + 2048]];
        int a3 = sC[sC[tid + 3072]];
        int a4 = (tid == 0) ? sC[sC[4096]] : 0;
        __syncthreads();
        sC[tid] = a0; sC[tid + 1024] = a1; sC[tid + 2048] = a2; sC[tid + 3072] = a3;
        if (tid == 0) sC[4096] = a4;
        __syncthreads();
    }

    int lcnt = 0;
    for (int x = tid; x < NN; x += 1024) {
        int c = sC[x];
        g_comp[x] = c;
        lcnt += (c == x);
        g_best[x] = ULLMAX;
    }
    #pragma unroll
    for (int o = 16; o; o >>= 1) lcnt += __shfl_xor_sync(0xffffffffu, lcnt, o);
    if ((tid & 31) == 0) sCnt[tid >> 5] = lcnt;
    __syncthreads();

    if (tid == 0) {
        float rs = 0.f; int cnt = 0;
        #pragma unroll
        for (int w = 0; w < 32; w++) { rs += sRed[w]; cnt += sCnt[w]; }
        g_total += rs;
        if (cnt <= 1) g_done = 1;
        out[0] = g_total;
    }
}

// ---------------- launch ----------------
extern "C" void kernel_launch(void* const* d_in, const int* in_sizes, int n_in,
                              void* d_out, int out_size)
{
    const float* batch  = (const float*)d_in[0];   // [16384,128]
    const float* output = (const float*)d_in[1];   // [4096,128]
    float* out = (float*)d_out;

    sqnorm_kernel<<<(NA + NB) / 8, 256>>>(batch, output);
    tobf_kernel<<<(NA + NB) * 64 / 256, 256>>>(batch, output);
    init_kernel<<<16, 1024>>>();

    dim3 g2(NB / 128, NA / 512);
    key_init_kernel<<<g2, 256>>>();

    dim3 g3(NB / 128, NB / 128);
    dbb_kernel<<<g3, 256>>>();

    round1_kernel<<<NB / 256, 256>>>(batch, output);
    merge_kernel<<<1, 1024>>>(output, out);

    for (int r = 0; r < 12; r++) {
        scan_kernel<<<NB / 8, 256>>>();
        merge_kernel<<<1, 1024>>>(output, out);
    }
}

// round 7
// speedup vs baseline: 9.8944x; 1.1744x over previous
#include <cuda_runtime.h>
#include <cuda_bf16.h>
#include <math_constants.h>

#define NA    4096
#define NB    4096
#define DIMK  128
#define NN    4097
#define SUPER 4096
#define ULLMAX 0xFFFFFFFFFFFFFFFFULL

typedef unsigned long long ull;

// ---------------- scratch ----------------
__device__ __align__(16) float    g_sqA[NA];
__device__ __align__(16) float    g_sqB[NB];
__device__ __align__(16) float    g_keyB[NB];      // exact sqrt(d^2(b, a*))
__device__ __align__(16) unsigned g_key2min[NB];   // exact fp32 bits of d^2(b, a*)
__device__ __align__(16) unsigned g_amin[NB];      // packed (approx d2 | a idx)
__device__ __align__(16) unsigned g_row1[NB];      // round-1 per-row min packed key
__device__ __align__(16) unsigned g_Abf[NA * 64];  // bf16x2 packed A points
__device__ __align__(16) unsigned g_Bbf[NB * 64];  // bf16x2 packed B points
__device__ __align__(16) unsigned g_KEY[(size_t)NB * NB];  // 64MB packed (d2w20|col12)
__device__ int  g_comp[NN];
__device__ ull  g_best[NN];
__device__ float g_total;
__device__ int   g_done;

// ---------------- K1: squared norms (exact fp32) ----------------
__global__ __launch_bounds__(256) void sqnorm_kernel(const float* __restrict__ batch,
                                                     const float* __restrict__ output) {
    int row  = blockIdx.x * 8 + (threadIdx.x >> 5);
    int lane = threadIdx.x & 31;
    const float* src = (row < NA) ? (batch + (size_t)row * DIMK)
                                  : (output + (size_t)(row - NA) * DIMK);
    float s = 0.f;
    #pragma unroll
    for (int k = lane; k < DIMK; k += 32) { float v = src[k]; s += v * v; }
    #pragma unroll
    for (int o = 16; o; o >>= 1) s += __shfl_down_sync(0xffffffffu, s, o);
    if (lane == 0) {
        if (row < NA) g_sqA[row] = s;
        else          g_sqB[row - NA] = s;
    }
}

// ---------------- convert to bf16x2 ----------------
__global__ __launch_bounds__(256) void tobf_kernel(const float* __restrict__ batch,
                                                   const float* __restrict__ output) {
    int idx = blockIdx.x * 256 + threadIdx.x;
    int row = idx >> 6, c = idx & 63;
    const float* src = (row < NA) ? (batch + (size_t)row * DIMK)
                                  : (output + (size_t)(row - NA) * DIMK);
    float2 v = *(const float2*)(src + c * 2);
    __nv_bfloat162 b = __float22bfloat162_rn(v);
    unsigned bits = *reinterpret_cast<unsigned*>(&b);
    if (row < NA) g_Abf[row * 64 + c] = bits;
    else          g_Bbf[(row - NA) * 64 + c] = bits;
}

// ---------------- init ----------------
__global__ __launch_bounds__(1024) void init_kernel() {
    int i = blockIdx.x * blockDim.x + threadIdx.x;
    int stride = gridDim.x * blockDim.x;
    for (int x = i; x < NN; x += stride) { g_comp[x] = x; g_best[x] = ULLMAX; }
    for (int x = i; x < NB; x += stride) { g_row1[x] = 0xFFFFFFFFu; g_amin[x] = 0xFFFFFFFFu; }
    if (i == 0) { g_total = 0.f; g_done = 0; }
}

// ---------------- MMA helpers ----------------
__device__ __forceinline__ void ldmx4(unsigned addr, unsigned& r0, unsigned& r1,
                                      unsigned& r2, unsigned& r3) {
    asm volatile("ldmatrix.sync.aligned.m8n8.x4.shared.b16 {%0,%1,%2,%3}, [%4];"
                 : "=r"(r0), "=r"(r1), "=r"(r2), "=r"(r3) : "r"(addr));
}
__device__ __forceinline__ void ldmx2(unsigned addr, unsigned& r0, unsigned& r1) {
    asm volatile("ldmatrix.sync.aligned.m8n8.x2.shared.b16 {%0,%1}, [%2];"
                 : "=r"(r0), "=r"(r1) : "r"(addr));
}
__device__ __forceinline__ void mma_bf16(float* c, unsigned a0, unsigned a1,
                                         unsigned a2, unsigned a3,
                                         unsigned b0, unsigned b1) {
    asm volatile("mma.sync.aligned.m16n8k16.row.col.f32.bf16.bf16.f32 "
                 "{%0,%1,%2,%3},{%4,%5,%6,%7},{%8,%9},{%0,%1,%2,%3};"
                 : "+f"(c[0]), "+f"(c[1]), "+f"(c[2]), "+f"(c[3])
                 : "r"(a0), "r"(a1), "r"(a2), "r"(a3), "r"(b0), "r"(b1));
}

// chunk layout: 128 rows x 32 bf16 (= 4 x 16B groups). phys 16B slot = r*4 + (g ^ (r&3)).
__device__ __forceinline__ void load_chunk_mma(uint4* sbuf, const unsigned* __restrict__ gsrc,
                                               int kc) {
    int tid = threadIdx.x;
    #pragma unroll
    for (int it = 0; it < 2; it++) {
        int f = tid + it * 256;
        int r = f >> 2, g = f & 3;
        uint4 v = *(const uint4*)(gsrc + (size_t)r * 64 + kc * 16 + g * 4);
        sbuf[r * 4 + (g ^ (r & 3))] = v;
    }
}
__device__ __forceinline__ unsigned chunk_addr(unsigned base, int row, int g) {
    return base + (unsigned)((row * 4 + (g ^ (row & 3))) << 4);
}

// load a-frag (m16 x k16) at (mt, kstep s) from chunk
__device__ __forceinline__ void afrag(unsigned base, int mt, int s, int lane,
                                      unsigned& a0, unsigned& a1, unsigned& a2, unsigned& a3) {
    int row = mt + (lane & 7) + ((lane >> 3) & 1) * 8;
    int g   = s * 2 + (lane >> 4);
    ldmx4(chunk_addr(base, row, g), a0, a1, a2, a3);
}
// load b-frag (k16 x n8) at (nt, kstep s)
__device__ __forceinline__ void bfrag(unsigned base, int nt, int s, int lane,
                                      unsigned& b0, unsigned& b1) {
    int l15 = lane & 15;
    int row = nt + (l15 & 7);
    int g   = s * 2 + ((l15 >> 3) & 1);
    ldmx2(chunk_addr(base, row, g), b0, b1);
}

// ---------------- K2: approx argmin_a d^2(b,a) via tensor cores ----------------
__global__ __launch_bounds__(256) void key_init_kernel()
{
    __shared__ __align__(16) uint4 sP[512];
    __shared__ __align__(16) uint4 sQ[512];
    __shared__ float sSqJ[128];

    const int tid = threadIdx.x, warp = tid >> 5, lane = tid & 31;
    const int m0 = blockIdx.y * 128;       // B rows
    const int n0 = blockIdx.x * 128;       // A cols
    const int wm = (warp & 3) * 32;        // warp tile: 32m x 64n
    const int wn = (warp >> 2) * 64;

    if (tid < 128) sSqJ[tid] = g_sqA[n0 + tid];

    unsigned basePu = (unsigned)__cvta_generic_to_shared(sP);
    unsigned baseQu = (unsigned)__cvta_generic_to_shared(sQ);

    float acc[2][8][4];
    #pragma unroll
    for (int mi = 0; mi < 2; mi++)
        #pragma unroll
        for (int j = 0; j < 8; j++)
            #pragma unroll
            for (int e = 0; e < 4; e++) acc[mi][j][e] = 0.f;

    for (int kc = 0; kc < 4; kc++) {
        __syncthreads();
        load_chunk_mma(sP, g_Bbf + (size_t)m0 * 64, kc);
        load_chunk_mma(sQ, g_Abf + (size_t)n0 * 64, kc);
        __syncthreads();
        #pragma unroll
        for (int s = 0; s < 2; s++) {
            unsigned a00, a01, a02, a03, a10, a11, a12, a13;
            afrag(basePu, wm,      s, lane, a00, a01, a02, a03);
            afrag(basePu, wm + 16, s, lane, a10, a11, a12, a13);
            #pragma unroll
            for (int j = 0; j < 8; j++) {
                unsigned b0, b1;
                bfrag(baseQu, wn + j * 8, s, lane, b0, b1);
                mma_bf16(acc[0][j], a00, a01, a02, a03, b0, b1);
                mma_bf16(acc[1][j], a10, a11, a12, a13, b0, b1);
            }
        }
    }

    // epilogue: pk = (d2 bits & ~0xFFF) | a_idx ; min over all n
    const int mlo = lane >> 2, ne = (lane & 3) * 2;
    float sqi[4];
    #pragma unroll
    for (int mi = 0; mi < 2; mi++) {
        sqi[mi * 2 + 0] = g_sqB[m0 + wm + mi * 16 + mlo];
        sqi[mi * 2 + 1] = g_sqB[m0 + wm + mi * 16 + 8 + mlo];
    }
    unsigned rmin[4] = {0xFFFFFFFFu, 0xFFFFFFFFu, 0xFFFFFFFFu, 0xFFFFFFFFu};
    #pragma unroll
    for (int mi = 0; mi < 2; mi++) {
        #pragma unroll
        for (int j = 0; j < 8; j++) {
            int nl = wn + j * 8 + ne;
            float sq0 = sSqJ[nl], sq1 = sSqJ[nl + 1];
            unsigned aj0 = (unsigned)(n0 + nl), aj1 = aj0 + 1;
            float d2;
            d2 = fmaxf(sqi[mi*2] + sq0 - 2.f * acc[mi][j][0], 0.f);
            rmin[mi*2]   = min(rmin[mi*2],   (__float_as_uint(d2) & 0xFFFFF000u) | aj0);
            d2 = fmaxf(sqi[mi*2] + sq1 - 2.f * acc[mi][j][1], 0.f);
            rmin[mi*2]   = min(rmin[mi*2],   (__float_as_uint(d2) & 0xFFFFF000u) | aj1);
            d2 = fmaxf(sqi[mi*2+1] + sq0 - 2.f * acc[mi][j][2], 0.f);
            rmin[mi*2+1] = min(rmin[mi*2+1], (__float_as_uint(d2) & 0xFFFFF000u) | aj0);
            d2 = fmaxf(sqi[mi*2+1] + sq1 - 2.f * acc[mi][j][3], 0.f);
            rmin[mi*2+1] = min(rmin[mi*2+1], (__float_as_uint(d2) & 0xFFFFF000u) | aj1);
        }
    }
    #pragma unroll
    for (int r = 0; r < 4; r++) {
        unsigned m = rmin[r];
        m = min(m, __shfl_xor_sync(0xffffffffu, m, 1));
        m = min(m, __shfl_xor_sync(0xffffffffu, m, 2));
        if ((lane & 3) == 0) {
            int row = m0 + wm + (r >> 1) * 16 + ((r & 1) ? 8 : 0) + mlo;
            atomicMin(&g_amin[row], m);
        }
    }
}

// ---------------- K3: packed d^2 key matrix via tensor cores (full grid) ----------------
__global__ __launch_bounds__(256) void dbb_kernel()
{
    __shared__ __align__(16) uint4 sP[512];
    __shared__ __align__(16) uint4 sQ[512];
    __shared__ float sSqJ[128];

    const int tid = threadIdx.x, warp = tid >> 5, lane = tid & 31;
    const int m0 = blockIdx.y * 128;
    const int n0 = blockIdx.x * 128;
    const int wm = (warp & 3) * 32;
    const int wn = (warp >> 2) * 64;

    if (tid < 128) sSqJ[tid] = g_sqB[n0 + tid];

    unsigned basePu = (unsigned)__cvta_generic_to_shared(sP);
    unsigned baseQu = (unsigned)__cvta_generic_to_shared(sQ);

    float acc[2][8][4];
    #pragma unroll
    for (int mi = 0; mi < 2; mi++)
        #pragma unroll
        for (int j = 0; j < 8; j++)
            #pragma unroll
            for (int e = 0; e < 4; e++) acc[mi][j][e] = 0.f;

    for (int kc = 0; kc < 4; kc++) {
        __syncthreads();
        load_chunk_mma(sP, g_Bbf + (size_t)m0 * 64, kc);
        load_chunk_mma(sQ, g_Bbf + (size_t)n0 * 64, kc);
        __syncthreads();
        #pragma unroll
        for (int s = 0; s < 2; s++) {
            unsigned a00, a01, a02, a03, a10, a11, a12, a13;
            afrag(basePu, wm,      s, lane, a00, a01, a02, a03);
            afrag(basePu, wm + 16, s, lane, a10, a11, a12, a13);
            #pragma unroll
            for (int j = 0; j < 8; j++) {
                unsigned b0, b1;
                bfrag(baseQu, wn + j * 8, s, lane, b0, b1);
                mma_bf16(acc[0][j], a00, a01, a02, a03, b0, b1);
                mma_bf16(acc[1][j], a10, a11, a12, a13, b0, b1);
            }
        }
    }

    const int mlo = lane >> 2, ne = (lane & 3) * 2;
    float sqi[4];
    int rowg[4];
    #pragma unroll
    for (int mi = 0; mi < 2; mi++) {
        rowg[mi*2]   = m0 + wm + mi * 16 + mlo;
        rowg[mi*2+1] = m0 + wm + mi * 16 + 8 + mlo;
        sqi[mi*2]    = g_sqB[rowg[mi*2]];
        sqi[mi*2+1]  = g_sqB[rowg[mi*2+1]];
    }
    unsigned rmin[4] = {0xFFFFFFFFu, 0xFFFFFFFFu, 0xFFFFFFFFu, 0xFFFFFFFFu};
    #pragma unroll
    for (int mi = 0; mi < 2; mi++) {
        #pragma unroll
        for (int j = 0; j < 8; j++) {
            int nl = wn + j * 8 + ne;
            int bj0 = n0 + nl, bj1 = bj0 + 1;
            float sq0 = sSqJ[nl], sq1 = sSqJ[nl + 1];
            #pragma unroll
            for (int h = 0; h < 2; h++) {       // h=0: row mlo ; h=1: row mlo+8
                int bi = rowg[mi*2 + h];
                float d20 = fmaxf(sqi[mi*2+h] + sq0 - 2.f * acc[mi][j][h*2+0], 0.f);
                float d21 = fmaxf(sqi[mi*2+h] + sq1 - 2.f * acc[mi][j][h*2+1], 0.f);
                unsigned pk0 = (__float_as_uint(d20) & 0xFFFFF000u) | (unsigned)bj0;
                unsigned pk1 = (__float_as_uint(d21) & 0xFFFFF000u) | (unsigned)bj1;
                if (bj0 != bi) rmin[mi*2+h] = min(rmin[mi*2+h], pk0);
                if (bj1 != bi) rmin[mi*2+h] = min(rmin[mi*2+h], pk1);
                *(uint2*)&g_KEY[(size_t)bi * NB + bj0] = make_uint2(pk0, pk1);
            }
        }
    }
    #pragma unroll
    for (int r = 0; r < 4; r++) {
        unsigned m = rmin[r];
        m = min(m, __shfl_xor_sync(0xffffffffu, m, 1));
        m = min(m, __shfl_xor_sync(0xffffffffu, m, 2));
        if ((lane & 3) == 0) atomicMin(&g_row1[rowg[r]], m);
    }
}

// ---------------- round 1: exact keyB repair + best assembly ----------------
__global__ __launch_bounds__(256) void round1_kernel(const float* __restrict__ batch,
                                                     const float* __restrict__ output) {
    int i = blockIdx.x * 256 + threadIdx.x;
    int a = (int)(g_amin[i] & 0xFFFu);

    const float4* pb = (const float4*)(output + (size_t)i * DIMK);
    const float4* pa = (const float4*)(batch  + (size_t)a * DIMK);
    float s = 0.f;
    #pragma unroll
    for (int q = 0; q < 32; q++) {
        float4 vb = pb[q], va = pa[q];
        float dx = vb.x - va.x, dy = vb.y - va.y, dz = vb.z - va.z, dw = vb.w - va.w;
        s += dx * dx + dy * dy + dz * dz + dw * dw;
    }
    unsigned d2b = __float_as_uint(s);
    g_key2min[i] = d2b;
    g_keyB[i]    = sqrtf(s);

    unsigned b32 = g_row1[i];
    unsigned j  = b32 & 0xFFFu;
    unsigned tw = b32 >> 12;
    unsigned lo = min((unsigned)i, j), hi = max((unsigned)i, j);
    ull kb = ((ull)tw << 26) | ((ull)lo << 13) | hi;

    unsigned tws = d2b >> 12;
    ull ksup = ((ull)tws << 26) | ((ull)(unsigned)i << 13) | SUPER;

    g_best[i] = min(kb, ksup);

    ull w = ksup;
    #pragma unroll
    for (int o = 16; o; o >>= 1) w = min(w, __shfl_xor_sync(0xffffffffu, w, o));
    if ((threadIdx.x & 31) == 0) atomicMin(&g_best[SUPER], w);
}

// ---------------- Boruvka scan (rounds >= 2) ----------------
__global__ __launch_bounds__(256) void scan_kernel() {
    if (g_done) return;
    __shared__ __align__(16) int sComp[NN + 3];
    const int tid = threadIdx.x;
    for (int x = tid; x < NN; x += 256) sComp[x] = g_comp[x];
    __syncthreads();

    const int warp = tid >> 5, lane = tid & 31;
    const int i    = blockIdx.x * 8 + warp;
    const int cu   = sComp[i];
    const int csup = sComp[SUPER];

    const uint4* row  = (const uint4*)(g_KEY + (size_t)i * NB);
    const int4*  cmp4 = (const int4*)sComp;

    unsigned best32 = 0xFFFFFFFFu;
    #pragma unroll 8
    for (int c = 0; c < 32; c++) {
        uint4 k  = row[c * 32 + lane];
        int4  cc = cmp4[c * 32 + lane];
        if (cc.x != cu) best32 = min(best32, k.x);
        if (cc.y != cu) best32 = min(best32, k.y);
        if (cc.z != cu) best32 = min(best32, k.z);
        if (cc.w != cu) best32 = min(best32, k.w);
    }
    #pragma unroll
    for (int o = 16; o; o >>= 1) best32 = min(best32, __shfl_xor_sync(0xffffffffu, best32, o));

    if (lane == 0) {
        ull kb = ULLMAX;
        if (best32 != 0xFFFFFFFFu) {
            unsigned j  = best32 & 0xFFFu;
            unsigned tw = best32 >> 12;
            unsigned lo = min((unsigned)i, j), hi = max((unsigned)i, j);
            kb = ((ull)tw << 26) | ((ull)lo << 13) | hi;
        }
        if (cu != csup) {
            unsigned tws = g_key2min[i] >> 12;
            ull ks = ((ull)tws << 26) | ((ull)(unsigned)i << 13) | SUPER;
            kb = min(kb, ks);
            atomicMin(&g_best[csup], ks);
        }
        if (kb != ULLMAX) atomicMin(&g_best[cu], kb);
    }
}

// ---------------- merge (exact fp32 weights) ----------------
__global__ __launch_bounds__(1024) void merge_kernel(const float* __restrict__ P,
                                                     float* __restrict__ out) {
    const int tid = threadIdx.x;
    __shared__ int   sC[NN];
    __shared__ int   sT[NN];
    __shared__ float sRed[32];
    __shared__ int   sCnt[32];

    if (g_done) { if (tid == 0) out[0] = g_total; return; }

    for (int x = tid; x < NN; x += 1024) sC[x] = g_comp[x];
    __syncthreads();

    for (int x = tid; x < NN; x += 1024) {
        int t = -1;
        if (sC[x] == x) {
            ull k = g_best[x];
            if (k != ULLMAX) {
                int u  = (int)((k >> 13) & 0x1FFFu);
                int v  = (int)(k & 0x1FFFu);
                int c1 = sC[u], c2 = sC[v];
                t = (c1 == x) ? c2 : c1;
            }
        }
        sT[x] = t;
    }
    __syncthreads();

    float lsum = 0.f;
    for (int x = tid; x < NN; x += 1024) {
        int t = sT[x];
        if (t >= 0) {
            ull k = g_best[x];
            bool mutual = (g_best[t] == k);
            if (!mutual || x < t) {
                int u = (int)((k >> 13) & 0x1FFFu);
                int v = (int)(k & 0x1FFFu);
                float w;
                if (v == SUPER) {
                    w = g_keyB[u];
                } else {
                    const float* pu = P + (size_t)u * DIMK;
                    const float* pv = P + (size_t)v * DIMK;
                    float s = 0.f;
                    #pragma unroll
                    for (int d = 0; d < DIMK; d++) { float df = pu[d] - pv[d]; s += df * df; }
                    w = sqrtf(s);
                }
                lsum += w;
            }
            if (!(mutual && x < t)) sC[x] = t;
        }
    }
    #pragma unroll
    for (int o = 16; o; o >>= 1) lsum += __shfl_xor_sync(0xffffffffu, lsum, o);
    if ((tid & 31) == 0) sRed[tid >> 5] = lsum;
    __syncthreads();

    for (int it = 0; it < 13; it++) {
        int a0 = sC[sC[tid]];
        int a1 = sC[sC[tid + 1024]];
        int a2 = sC[sC[tid + 2048]];
        int a3 = sC[sC[tid + 3072]];
        int a4 = (tid == 0) ? sC[sC[4096]] : 0;
        __syncthreads();
        sC[tid] = a0; sC[tid + 1024] = a1; sC[tid + 2048] = a2; sC[tid + 3072] = a3;
        if (tid == 0) sC[4096] = a4;
        __syncthreads();
    }

    int lcnt = 0;
    for (int x = tid; x < NN; x += 1024) {
        int c = sC[x];
        g_comp[x] = c;
        lcnt += (c == x);
        g_best[x] = ULLMAX;
    }
    #pragma unroll
    for (int o = 16; o; o >>= 1) lcnt += __shfl_xor_sync(0xffffffffu, lcnt, o);
    if ((tid & 31) == 0) sCnt[tid >> 5] = lcnt;
    __syncthreads();

    if (tid == 0) {
        float rs = 0.f; int cnt = 0;
        #pragma unroll
        for (int w = 0; w < 32; w++) { rs += sRed[w]; cnt += sCnt[w]; }
        g_total += rs;
        if (cnt <= 1) g_done = 1;
        out[0] = g_total;
    }
}

// ---------------- launch ----------------
extern "C" void kernel_launch(void* const* d_in, const int* in_sizes, int n_in,
                              void* d_out, int out_size)
{
    const float* batch  = (const float*)d_in[0];   // [16384,128]
    const float* output = (const float*)d_in[1];   // [4096,128]
    float* out = (float*)d_out;

    sqnorm_kernel<<<(NA + NB) / 8, 256>>>(batch, output);
    tobf_kernel<<<(NA + NB) * 64 / 256, 256>>>(batch, output);
    init_kernel<<<16, 1024>>>();

    dim3 g2(NA / 128, NB / 128);
    key_init_kernel<<<g2, 256>>>();

    dim3 g3(NB / 128, NB / 128);
    dbb_kernel<<<g3, 256>>>();

    round1_kernel<<<NB / 256, 256>>>(batch, output);
    merge_kernel<<<1, 1024>>>(output, out);

    for (int r = 0; r < 12; r++) {
        scan_kernel<<<NB / 8, 256>>>();
        merge_kernel<<<1, 1024>>>(output, out);
    }
}

// round 8
// speedup vs baseline: 19.4830x; 1.9691x over previous
#include <cuda_runtime.h>
#include <cuda_bf16.h>
#include <math_constants.h>

#define NA    4096
#define NB    4096
#define DIMK  128
#define NN    4097
#define SUPER 4096
#define ULLMAX 0xFFFFFFFFFFFFFFFFULL
#define NBLK  296          // persistent grid: 2 blocks/SM guaranteed resident

typedef unsigned long long ull;

// ---------------- scratch ----------------
__device__ __align__(16) float    g_sqA[NA];
__device__ __align__(16) float    g_sqB[NB];
__device__ __align__(16) float    g_keyB[NB];      // exact sqrt(d^2(b, a*))
__device__ __align__(16) unsigned g_key2min[NB];   // exact fp32 bits of d^2(b, a*)
__device__ __align__(16) unsigned g_amin[NB];      // packed (approx d2 | a idx)
__device__ __align__(16) unsigned g_row1[NB];      // round-1 per-row min packed key
__device__ __align__(16) unsigned g_Abf[NA * 64];  // bf16x2 packed A points
__device__ __align__(16) unsigned g_Bbf[NB * 64];  // bf16x2 packed B points
__device__ __align__(16) unsigned g_KEY[(size_t)NB * NB];  // 64MB packed (d2w20|col12)
__device__ int  g_comp[NN];
__device__ ull  g_best[NN];
__device__ float g_total;
__device__ int   g_done;
__device__ unsigned          g_barcnt;
__device__ volatile unsigned g_barphase;

// ---------------- prep: squared norms + bf16x2 pack, one pass ----------------
__global__ __launch_bounds__(256) void prep_kernel(const float* __restrict__ batch,
                                                   const float* __restrict__ output) {
    int row  = blockIdx.x * 8 + (threadIdx.x >> 5);   // 1024 blocks -> 8192 rows
    int lane = threadIdx.x & 31;
    bool isA = row < NA;
    const float* src = isA ? (batch + (size_t)row * DIMK)
                           : (output + (size_t)(row - NA) * DIMK);
    float4 v = ((const float4*)src)[lane];
    float s = v.x * v.x + v.y * v.y + v.z * v.z + v.w * v.w;

    __nv_bfloat162 b0 = __float22bfloat162_rn(make_float2(v.x, v.y));
    __nv_bfloat162 b1 = __float22bfloat162_rn(make_float2(v.z, v.w));
    uint2 w;
    w.x = *reinterpret_cast<unsigned*>(&b0);
    w.y = *reinterpret_cast<unsigned*>(&b1);
    unsigned* dst = isA ? (g_Abf + (size_t)row * 64) : (g_Bbf + (size_t)(row - NA) * 64);
    *(uint2*)(dst + lane * 2) = w;

    #pragma unroll
    for (int o = 16; o; o >>= 1) s += __shfl_down_sync(0xffffffffu, s, o);
    if (lane == 0) {
        if (isA) g_sqA[row] = s;
        else     g_sqB[row - NA] = s;
    }
}

// ---------------- init ----------------
__global__ __launch_bounds__(1024) void init_kernel() {
    int i = blockIdx.x * blockDim.x + threadIdx.x;
    int stride = gridDim.x * blockDim.x;
    for (int x = i; x < NN; x += stride) { g_comp[x] = x; g_best[x] = ULLMAX; }
    for (int x = i; x < NB; x += stride) { g_row1[x] = 0xFFFFFFFFu; g_amin[x] = 0xFFFFFFFFu; }
    if (i == 0) { g_total = 0.f; g_done = 0; g_barcnt = 0u; }
}

// ---------------- MMA helpers ----------------
__device__ __forceinline__ void ldmx4(unsigned addr, unsigned& r0, unsigned& r1,
                                      unsigned& r2, unsigned& r3) {
    asm volatile("ldmatrix.sync.aligned.m8n8.x4.shared.b16 {%0,%1,%2,%3}, [%4];"
                 : "=r"(r0), "=r"(r1), "=r"(r2), "=r"(r3) : "r"(addr));
}
__device__ __forceinline__ void ldmx2(unsigned addr, unsigned& r0, unsigned& r1) {
    asm volatile("ldmatrix.sync.aligned.m8n8.x2.shared.b16 {%0,%1}, [%2];"
                 : "=r"(r0), "=r"(r1) : "r"(addr));
}
__device__ __forceinline__ void mma_bf16(float* c, unsigned a0, unsigned a1,
                                         unsigned a2, unsigned a3,
                                         unsigned b0, unsigned b1) {
    asm volatile("mma.sync.aligned.m16n8k16.row.col.f32.bf16.bf16.f32 "
                 "{%0,%1,%2,%3},{%4,%5,%6,%7},{%8,%9},{%0,%1,%2,%3};"
                 : "+f"(c[0]), "+f"(c[1]), "+f"(c[2]), "+f"(c[3])
                 : "r"(a0), "r"(a1), "r"(a2), "r"(a3), "r"(b0), "r"(b1));
}

// chunk layout: 128 rows x 32 bf16 (= 4 x 16B groups). phys 16B slot = r*4 + (g ^ (r&3)).
__device__ __forceinline__ void load_chunk_mma(uint4* sbuf, const unsigned* __restrict__ gsrc,
                                               int kc) {
    int tid = threadIdx.x;
    #pragma unroll
    for (int it = 0; it < 2; it++) {
        int f = tid + it * 256;
        int r = f >> 2, g = f & 3;
        uint4 v = *(const uint4*)(gsrc + (size_t)r * 64 + kc * 16 + g * 4);
        sbuf[r * 4 + (g ^ (r & 3))] = v;
    }
}
__device__ __forceinline__ unsigned chunk_addr(unsigned base, int row, int g) {
    return base + (unsigned)((row * 4 + (g ^ (row & 3))) << 4);
}
__device__ __forceinline__ void afrag(unsigned base, int mt, int s, int lane,
                                      unsigned& a0, unsigned& a1, unsigned& a2, unsigned& a3) {
    int row = mt + (lane & 7) + ((lane >> 3) & 1) * 8;
    int g   = s * 2 + (lane >> 4);
    ldmx4(chunk_addr(base, row, g), a0, a1, a2, a3);
}
__device__ __forceinline__ void bfrag(unsigned base, int nt, int s, int lane,
                                      unsigned& b0, unsigned& b1) {
    int l15 = lane & 15;
    int row = nt + (l15 & 7);
    int g   = s * 2 + ((l15 >> 3) & 1);
    ldmx2(chunk_addr(base, row, g), b0, b1);
}

// ---------------- K2: approx argmin_a d^2(b,a) via tensor cores ----------------
__global__ __launch_bounds__(256) void key_init_kernel()
{
    __shared__ __align__(16) uint4 sP[512];
    __shared__ __align__(16) uint4 sQ[512];
    __shared__ float sSqJ[128];

    const int tid = threadIdx.x, warp = tid >> 5, lane = tid & 31;
    const int m0 = blockIdx.y * 128;       // B rows
    const int n0 = blockIdx.x * 128;       // A cols
    const int wm = (warp & 3) * 32;
    const int wn = (warp >> 2) * 64;

    if (tid < 128) sSqJ[tid] = g_sqA[n0 + tid];

    unsigned basePu = (unsigned)__cvta_generic_to_shared(sP);
    unsigned baseQu = (unsigned)__cvta_generic_to_shared(sQ);

    float acc[2][8][4];
    #pragma unroll
    for (int mi = 0; mi < 2; mi++)
        #pragma unroll
        for (int j = 0; j < 8; j++)
            #pragma unroll
            for (int e = 0; e < 4; e++) acc[mi][j][e] = 0.f;

    for (int kc = 0; kc < 4; kc++) {
        __syncthreads();
        load_chunk_mma(sP, g_Bbf + (size_t)m0 * 64, kc);
        load_chunk_mma(sQ, g_Abf + (size_t)n0 * 64, kc);
        __syncthreads();
        #pragma unroll
        for (int s = 0; s < 2; s++) {
            unsigned a00, a01, a02, a03, a10, a11, a12, a13;
            afrag(basePu, wm,      s, lane, a00, a01, a02, a03);
            afrag(basePu, wm + 16, s, lane, a10, a11, a12, a13);
            #pragma unroll
            for (int j = 0; j < 8; j++) {
                unsigned b0, b1;
                bfrag(baseQu, wn + j * 8, s, lane, b0, b1);
                mma_bf16(acc[0][j], a00, a01, a02, a03, b0, b1);
                mma_bf16(acc[1][j], a10, a11, a12, a13, b0, b1);
            }
        }
    }

    const int mlo = lane >> 2, ne = (lane & 3) * 2;
    float sqi[4];
    #pragma unroll
    for (int mi = 0; mi < 2; mi++) {
        sqi[mi * 2 + 0] = g_sqB[m0 + wm + mi * 16 + mlo];
        sqi[mi * 2 + 1] = g_sqB[m0 + wm + mi * 16 + 8 + mlo];
    }
    unsigned rmin[4] = {0xFFFFFFFFu, 0xFFFFFFFFu, 0xFFFFFFFFu, 0xFFFFFFFFu};
    #pragma unroll
    for (int mi = 0; mi < 2; mi++) {
        #pragma unroll
        for (int j = 0; j < 8; j++) {
            int nl = wn + j * 8 + ne;
            float sq0 = sSqJ[nl], sq1 = sSqJ[nl + 1];
            unsigned aj0 = (unsigned)(n0 + nl), aj1 = aj0 + 1;
            float d2;
            d2 = fmaxf(sqi[mi*2] + sq0 - 2.f * acc[mi][j][0], 0.f);
            rmin[mi*2]   = min(rmin[mi*2],   (__float_as_uint(d2) & 0xFFFFF000u) | aj0);
            d2 = fmaxf(sqi[mi*2] + sq1 - 2.f * acc[mi][j][1], 0.f);
            rmin[mi*2]   = min(rmin[mi*2],   (__float_as_uint(d2) & 0xFFFFF000u) | aj1);
            d2 = fmaxf(sqi[mi*2+1] + sq0 - 2.f * acc[mi][j][2], 0.f);
            rmin[mi*2+1] = min(rmin[mi*2+1], (__float_as_uint(d2) & 0xFFFFF000u) | aj0);
            d2 = fmaxf(sqi[mi*2+1] + sq1 - 2.f * acc[mi][j][3], 0.f);
            rmin[mi*2+1] = min(rmin[mi*2+1], (__float_as_uint(d2) & 0xFFFFF000u) | aj1);
        }
    }
    #pragma unroll
    for (int r = 0; r < 4; r++) {
        unsigned m = rmin[r];
        m = min(m, __shfl_xor_sync(0xffffffffu, m, 1));
        m = min(m, __shfl_xor_sync(0xffffffffu, m, 2));
        if ((lane & 3) == 0) {
            int row = m0 + wm + (r >> 1) * 16 + ((r & 1) ? 8 : 0) + mlo;
            atomicMin(&g_amin[row], m);
        }
    }
}

// ---------------- K3: packed d^2 key matrix via tensor cores ----------------
__global__ __launch_bounds__(256) void dbb_kernel()
{
    __shared__ __align__(16) uint4 sP[512];
    __shared__ __align__(16) uint4 sQ[512];
    __shared__ float sSqJ[128];

    const int tid = threadIdx.x, warp = tid >> 5, lane = tid & 31;
    const int m0 = blockIdx.y * 128;
    const int n0 = blockIdx.x * 128;
    const int wm = (warp & 3) * 32;
    const int wn = (warp >> 2) * 64;

    if (tid < 128) sSqJ[tid] = g_sqB[n0 + tid];

    unsigned basePu = (unsigned)__cvta_generic_to_shared(sP);
    unsigned baseQu = (unsigned)__cvta_generic_to_shared(sQ);

    float acc[2][8][4];
    #pragma unroll
    for (int mi = 0; mi < 2; mi++)
        #pragma unroll
        for (int j = 0; j < 8; j++)
            #pragma unroll
            for (int e = 0; e < 4; e++) acc[mi][j][e] = 0.f;

    for (int kc = 0; kc < 4; kc++) {
        __syncthreads();
        load_chunk_mma(sP, g_Bbf + (size_t)m0 * 64, kc);
        load_chunk_mma(sQ, g_Bbf + (size_t)n0 * 64, kc);
        __syncthreads();
        #pragma unroll
        for (int s = 0; s < 2; s++) {
            unsigned a00, a01, a02, a03, a10, a11, a12, a13;
            afrag(basePu, wm,      s, lane, a00, a01, a02, a03);
            afrag(basePu, wm + 16, s, lane, a10, a11, a12, a13);
            #pragma unroll
            for (int j = 0; j < 8; j++) {
                unsigned b0, b1;
                bfrag(baseQu, wn + j * 8, s, lane, b0, b1);
                mma_bf16(acc[0][j], a00, a01, a02, a03, b0, b1);
                mma_bf16(acc[1][j], a10, a11, a12, a13, b0, b1);
            }
        }
    }

    const int mlo = lane >> 2, ne = (lane & 3) * 2;
    float sqi[4];
    int rowg[4];
    #pragma unroll
    for (int mi = 0; mi < 2; mi++) {
        rowg[mi*2]   = m0 + wm + mi * 16 + mlo;
        rowg[mi*2+1] = m0 + wm + mi * 16 + 8 + mlo;
        sqi[mi*2]    = g_sqB[rowg[mi*2]];
        sqi[mi*2+1]  = g_sqB[rowg[mi*2+1]];
    }
    unsigned rmin[4] = {0xFFFFFFFFu, 0xFFFFFFFFu, 0xFFFFFFFFu, 0xFFFFFFFFu};
    #pragma unroll
    for (int mi = 0; mi < 2; mi++) {
        #pragma unroll
        for (int j = 0; j < 8; j++) {
            int nl = wn + j * 8 + ne;
            int bj0 = n0 + nl, bj1 = bj0 + 1;
            float sq0 = sSqJ[nl], sq1 = sSqJ[nl + 1];
            #pragma unroll
            for (int h = 0; h < 2; h++) {
                int bi = rowg[mi*2 + h];
                float d20 = fmaxf(sqi[mi*2+h] + sq0 - 2.f * acc[mi][j][h*2+0], 0.f);
                float d21 = fmaxf(sqi[mi*2+h] + sq1 - 2.f * acc[mi][j][h*2+1], 0.f);
                unsigned pk0 = (__float_as_uint(d20) & 0xFFFFF000u) | (unsigned)bj0;
                unsigned pk1 = (__float_as_uint(d21) & 0xFFFFF000u) | (unsigned)bj1;
                if (bj0 != bi) rmin[mi*2+h] = min(rmin[mi*2+h], pk0);
                if (bj1 != bi) rmin[mi*2+h] = min(rmin[mi*2+h], pk1);
                *(uint2*)&g_KEY[(size_t)bi * NB + bj0] = make_uint2(pk0, pk1);
            }
        }
    }
    #pragma unroll
    for (int r = 0; r < 4; r++) {
        unsigned m = rmin[r];
        m = min(m, __shfl_xor_sync(0xffffffffu, m, 1));
        m = min(m, __shfl_xor_sync(0xffffffffu, m, 2));
        if ((lane & 3) == 0) atomicMin(&g_row1[rowg[r]], m);
    }
}

// ---------------- round 1: exact keyB repair + best assembly ----------------
__global__ __launch_bounds__(256) void round1_kernel(const float* __restrict__ batch,
                                                     const float* __restrict__ output) {
    int i = blockIdx.x * 256 + threadIdx.x;
    int a = (int)(g_amin[i] & 0xFFFu);

    const float4* pb = (const float4*)(output + (size_t)i * DIMK);
    const float4* pa = (const float4*)(batch  + (size_t)a * DIMK);
    float s = 0.f;
    #pragma unroll
    for (int q = 0; q < 32; q++) {
        float4 vb = pb[q], va = pa[q];
        float dx = vb.x - va.x, dy = vb.y - va.y, dz = vb.z - va.z, dw = vb.w - va.w;
        s += dx * dx + dy * dy + dz * dz + dw * dw;
    }
    unsigned d2b = __float_as_uint(s);
    g_key2min[i] = d2b;
    g_keyB[i]    = sqrtf(s);

    unsigned b32 = g_row1[i];
    unsigned j  = b32 & 0xFFFu;
    unsigned tw = b32 >> 12;
    unsigned lo = min((unsigned)i, j), hi = max((unsigned)i, j);
    ull kb = ((ull)tw << 26) | ((ull)lo << 13) | hi;

    unsigned tws = d2b >> 12;
    ull ksup = ((ull)tws << 26) | ((ull)(unsigned)i << 13) | SUPER;

    g_best[i] = min(kb, ksup);

    ull w = ksup;
    #pragma unroll
    for (int o = 16; o; o >>= 1) w = min(w, __shfl_xor_sync(0xffffffffu, w, o));
    if ((threadIdx.x & 31) == 0) atomicMin(&g_best[SUPER], w);
}

// ---------------- persistent Boruvka: grid barrier ----------------
__device__ __forceinline__ void grid_sync() {
    __syncthreads();
    if (threadIdx.x == 0) {
        __threadfence();
        unsigned gen = g_barphase;               // read BEFORE arriving
        if (atomicAdd(&g_barcnt, 1u) == (unsigned)gridDim.x - 1u) {
            g_barcnt = 0u;
            __threadfence();
            g_barphase = gen + 1u;
        } else {
            while (g_barphase == gen) { __nanosleep(32); }
        }
    }
    __syncthreads();
}

// scan all rows this block owns (comp snapshot in sC)
__device__ void scan_rows(int* sC, ull* sSup) {
    const int tid = threadIdx.x;
    for (int x = tid; x < NN; x += 256) sC[x] = __ldcg(&g_comp[x]);
    __syncthreads();

    const int warp = tid >> 5, lane = tid & 31;
    const int csup = sC[SUPER];
    const int4* cmp4 = (const int4*)sC;

    ull mySup = ULLMAX;
    for (int i = blockIdx.x * 8 + warp; i < NB; i += NBLK * 8) {
        const int cu = sC[i];
        const uint4* row = (const uint4*)(g_KEY + (size_t)i * NB);
        unsigned best32 = 0xFFFFFFFFu;
        #pragma unroll 8
        for (int c = 0; c < 32; c++) {
            uint4 k  = row[c * 32 + lane];
            int4  cc = cmp4[c * 32 + lane];
            if (cc.x != cu) best32 = min(best32, k.x);
            if (cc.y != cu) best32 = min(best32, k.y);
            if (cc.z != cu) best32 = min(best32, k.z);
            if (cc.w != cu) best32 = min(best32, k.w);
        }
        #pragma unroll
        for (int o = 16; o; o >>= 1) best32 = min(best32, __shfl_xor_sync(0xffffffffu, best32, o));

        if (lane == 0) {
            ull kb = ULLMAX;
            if (best32 != 0xFFFFFFFFu) {
                unsigned j  = best32 & 0xFFFu;
                unsigned tw = best32 >> 12;
                unsigned lo = min((unsigned)i, j), hi = max((unsigned)i, j);
                kb = ((ull)tw << 26) | ((ull)lo << 13) | hi;
            }
            if (cu != csup) {
                unsigned tws = g_key2min[i] >> 12;
                ull ks = ((ull)tws << 26) | ((ull)(unsigned)i << 13) | SUPER;
                kb = min(kb, ks);
                mySup = min(mySup, ks);
            }
            if (kb != ULLMAX) atomicMin(&g_best[cu], kb);
        }
    }
    if (lane == 0) sSup[warp] = mySup;
    __syncthreads();
    if (tid == 0) {
        ull m = ULLMAX;
        #pragma unroll
        for (int w = 0; w < 8; w++) m = min(m, sSup[w]);
        if (m != ULLMAX) atomicMin(&g_best[csup], m);
    }
    __syncthreads();
}

// merge on block 0 (256 threads)
__device__ void merge_block(const float* __restrict__ P, float* __restrict__ out,
                            int* sC, int* sT, float* sRed, int* sCnt) {
    const int tid = threadIdx.x, warp = tid >> 5, lane = tid & 31;

    for (int x = tid; x < NN; x += 256) sC[x] = __ldcg(&g_comp[x]);
    __syncthreads();

    for (int x = tid; x < NN; x += 256) {
        int t = -1;
        if (sC[x] == x) {
            ull k = __ldcg(&g_best[x]);
            if (k != ULLMAX) {
                int u  = (int)((k >> 13) & 0x1FFFu);
                int v  = (int)(k & 0x1FFFu);
                int c1 = sC[u], c2 = sC[v];
                t = (c1 == x) ? c2 : c1;
            }
        }
        sT[x] = t;
    }
    __syncthreads();

    float lsum = 0.f;
    for (int x = tid; x < NN; x += 256) {
        int t = sT[x];
        if (t >= 0) {
            ull k = __ldcg(&g_best[x]);
            bool mutual = (__ldcg(&g_best[t]) == k);
            if (!mutual || x < t) {
                int u = (int)((k >> 13) & 0x1FFFu);
                int v = (int)(k & 0x1FFFu);
                float w;
                if (v == SUPER) {
                    w = g_keyB[u];
                } else {
                    const float4* pu = (const float4*)(P + (size_t)u * DIMK);
                    const float4* pv = (const float4*)(P + (size_t)v * DIMK);
                    float s = 0.f;
                    #pragma unroll 8
                    for (int q = 0; q < 32; q++) {
                        float4 a = pu[q], b = pv[q];
                        float dx = a.x - b.x, dy = a.y - b.y, dz = a.z - b.z, dw = a.w - b.w;
                        s += dx * dx + dy * dy + dz * dz + dw * dw;
                    }
                    w = sqrtf(s);
                }
                lsum += w;
            }
            if (!(mutual && x < t)) sC[x] = t;
        }
    }
    #pragma unroll
    for (int o = 16; o; o >>= 1) lsum += __shfl_xor_sync(0xffffffffu, lsum, o);
    if (lane == 0) sRed[warp] = lsum;
    __syncthreads();

    // pointer jumping: 13 halvings, double-buffered through registers
    for (int it = 0; it < 13; it++) {
        int v[17];
        #pragma unroll
        for (int q = 0; q < 17; q++) {
            int x = tid + q * 256;
            v[q] = (x < NN) ? sC[sC[x]] : 0;
        }
        __syncthreads();
        #pragma unroll
        for (int q = 0; q < 17; q++) {
            int x = tid + q * 256;
            if (x < NN) sC[x] = v[q];
        }
        __syncthreads();
    }

    int lcnt = 0;
    for (int x = tid; x < NN; x += 256) {
        int c = sC[x];
        g_comp[x] = c;
        lcnt += (c == x);
        g_best[x] = ULLMAX;
    }
    #pragma unroll
    for (int o = 16; o; o >>= 1) lcnt += __shfl_xor_sync(0xffffffffu, lcnt, o);
    if (lane == 0) sCnt[warp] = lcnt;
    __syncthreads();

    if (tid == 0) {
        float rs = 0.f; int cnt = 0;
        #pragma unroll
        for (int w = 0; w < 8; w++) { rs += sRed[w]; cnt += sCnt[w]; }
        g_total += rs;
        if (cnt <= 1) g_done = 1;
        out[0] = g_total;
    }
    __syncthreads();
}

__global__ __launch_bounds__(256, 2) void boruvka_kernel(const float* __restrict__ P,
                                                         float* __restrict__ out) {
    __shared__ __align__(16) int  sA[NN + 3];
    __shared__ __align__(16) int  sB[NN + 3];
    __shared__ ull   sSup[8];
    __shared__ float sRed[8];
    __shared__ int   sCnt[8];

    for (int round = 0; round < 13; round++) {
        if (blockIdx.x == 0) merge_block(P, out, sA, sB, sRed, sCnt);
        grid_sync();
        if (__ldcg(&g_done)) return;
        scan_rows(sA, sSup);
        grid_sync();
    }
}

// ---------------- launch ----------------
extern "C" void kernel_launch(void* const* d_in, const int* in_sizes, int n_in,
                              void* d_out, int out_size)
{
    const float* batch  = (const float*)d_in[0];   // [16384,128]
    const float* output = (const float*)d_in[1];   // [4096,128]
    float* out = (float*)d_out;

    prep_kernel<<<(NA + NB) / 8, 256>>>(batch, output);
    init_kernel<<<16, 1024>>>();

    dim3 g2(NA / 128, NB / 128);
    key_init_kernel<<<g2, 256>>>();

    dim3 g3(NB / 128, NB / 128);
    dbb_kernel<<<g3, 256>>>();

    round1_kernel<<<NB / 256, 256>>>(batch, output);

    boruvka_kernel<<<NBLK, 256>>>(output, out);
}